// round 1
// baseline (speedup 1.0000x reference)
#include <cuda_runtime.h>
#include <cstdint>

#define H    512
#define NLAY 4
#define N2   32
#define BSZ  8
#define LSEQ 4096
#define LN_EPS 1e-5f

// ---- static scratch (allocation-free rule) ----
__device__ float g_xA[(size_t)BSZ * H * LSEQ];      // 64MB  activations (B,H,L)
__device__ float g_xB[(size_t)BSZ * H * LSEQ];      // 64MB  ping-pong
__device__ float g_Y [(size_t)BSZ * H * LSEQ];      // 64MB  gelu(ssm out)
__device__ float g_Z [(size_t)BSZ * 2 * H * LSEQ];  // 128MB conv output

// ================= transpose (B,L,H) -> (B,H,L) =================
__global__ void transpose_in(const float* __restrict__ x) {
    __shared__ float tile[32][33];
    int b = blockIdx.z;
    int h0 = blockIdx.x * 32, l0 = blockIdx.y * 32;
    int tx = threadIdx.x, ty = threadIdx.y;
#pragma unroll
    for (int j = 0; j < 32; j += 8)
        tile[ty + j][tx] = x[((size_t)b * LSEQ + (l0 + ty + j)) * H + h0 + tx];
    __syncthreads();
#pragma unroll
    for (int j = 0; j < 32; j += 8)
        g_xA[((size_t)b * H + (h0 + ty + j)) * LSEQ + l0 + tx] = tile[tx][ty + j];
}

// ================= transpose (B,H,L) -> (B,L,H) =================
__global__ void transpose_out(float* __restrict__ out, int ping) {
    const float* xin = ping ? g_xB : g_xA;
    __shared__ float tile[32][33];
    int b = blockIdx.z;
    int l0 = blockIdx.x * 32, h0 = blockIdx.y * 32;
    int tx = threadIdx.x, ty = threadIdx.y;
#pragma unroll
    for (int j = 0; j < 32; j += 8)
        tile[ty + j][tx] = xin[((size_t)b * H + (h0 + ty + j)) * LSEQ + l0 + tx];
    __syncthreads();
#pragma unroll
    for (int j = 0; j < 32; j += 8)
        out[((size_t)b * LSEQ + (l0 + tx)) * H + h0 + ty + j] = tile[ty + j][tx];
}

// ================= SSM scan: 8 lanes per (b,h), 4 complex states/lane ========
__global__ __launch_bounds__(128) void ssm_scan(
    const float* __restrict__ log_dt, const float* __restrict__ A_imag,
    const float* __restrict__ log_A_real, const float* __restrict__ Cp,
    const float* __restrict__ Dp, int layer, int ping)
{
    const float* xin = ping ? g_xB : g_xA;
    int tid = blockIdx.x * blockDim.x + threadIdx.x;
    int group = tid >> 3;        // 0 .. B*H-1
    int li = tid & 7;            // lane in group
    int lane = threadIdx.x & 31;
    int h = group & (H - 1);

    float dt = expf(log_dt[layer * H + h]);
    int pbase = (layer * H + h) * N2 + li * 4;
    float4 aim = *(const float4*)(A_imag + pbase);
    float4 lar = *(const float4*)(log_A_real + pbase);
    float4 c01 = *(const float4*)(Cp + 2 * pbase);
    float4 c23 = *(const float4*)(Cp + 2 * pbase + 4);
    float aimv[4] = {aim.x, aim.y, aim.z, aim.w};
    float larv[4] = {lar.x, lar.y, lar.z, lar.w};
    float ccr[4]  = {c01.x, c01.z, c23.x, c23.z};
    float cci[4]  = {c01.y, c01.w, c23.y, c23.w};

    float w_re[4], w_im[4], cf_re[4], cf_im[4];
#pragma unroll
    for (int j = 0; j < 4; j++) {
        float Are = -expf(larv[j]);
        float Aim = aimv[j];
        float dre = Are * dt, dim = Aim * dt;
        float e = expf(dre);
        float wr = e * cosf(dim), wi = e * sinf(dim);
        w_re[j] = wr; w_im[j] = wi;
        float nr = wr - 1.0f, ni = wi;                 // exp(dA)-1
        float tr = ccr[j] * nr - cci[j] * ni;          // C*(exp(dA)-1)
        float ti = ccr[j] * ni + cci[j] * nr;
        float inv = 2.0f / (Are * Are + Aim * Aim);    // fold the "2*Re" factor
        cf_re[j] = (tr * Are + ti * Aim) * inv;        // * conj(A)/|A|^2
        cf_im[j] = (ti * Are - tr * Aim) * inv;
    }
    float Dh = Dp[layer * H + h];

    const float* urow = xin + (size_t)group * LSEQ;
    float* yrow = g_Y + (size_t)group * LSEQ;

    float sre[4] = {0.f, 0.f, 0.f, 0.f}, sim[4] = {0.f, 0.f, 0.f, 0.f};
    float ucur = urow[li];
    for (int l0 = 0; l0 < LSEQ; l0 += 8) {
        float unext = (l0 + 8 < LSEQ) ? urow[l0 + 8 + li] : 0.0f;
        float yl = 0.0f;
#pragma unroll
        for (int k = 0; k < 8; k++) {
            float u = __shfl_sync(0xffffffffu, ucur, (lane & 24) | k);
            float c = 0.0f;
#pragma unroll
            for (int j = 0; j < 4; j++) {
                float tim = fmaf(w_im[j], sre[j], w_re[j] * sim[j]);
                float tre = fmaf(w_re[j], sre[j], u);
                tre = fmaf(-w_im[j], sim[j], tre);
                sre[j] = tre; sim[j] = tim;
                c = fmaf(cf_re[j], tre, c);
                c = fmaf(-cf_im[j], tim, c);
            }
            c += __shfl_xor_sync(0xffffffffu, c, 1);
            c += __shfl_xor_sync(0xffffffffu, c, 2);
            c += __shfl_xor_sync(0xffffffffu, c, 4);
            if (k == li) yl = fmaf(Dh, u, c);
        }
        // exact GELU (erf form), coalesced 32B store per group
        float gl = 0.5f * yl * (1.0f + erff(yl * 0.70710678118654752f));
        yrow[l0 + li] = gl;
        ucur = unext;
    }
}

// ================= 1x1 conv GEMM: Z = W @ Y  (split-tf32, fp32 accuracy) ====
#define BM 128
#define BN 64
#define BK 16

__device__ __forceinline__ unsigned f2tf32(float x) {
    unsigned r;
    asm("cvt.rna.tf32.f32 %0, %1;" : "=r"(r) : "f"(x));
    return r;
}
__device__ __forceinline__ void mma_tf32(float* d, const unsigned* a, const unsigned* bf) {
    asm volatile(
        "mma.sync.aligned.m16n8k8.row.col.f32.tf32.tf32.f32 "
        "{%0,%1,%2,%3}, {%4,%5,%6,%7}, {%8,%9}, {%0,%1,%2,%3};"
        : "+f"(d[0]), "+f"(d[1]), "+f"(d[2]), "+f"(d[3])
        : "r"(a[0]), "r"(a[1]), "r"(a[2]), "r"(a[3]), "r"(bf[0]), "r"(bf[1]));
}

__global__ __launch_bounds__(256) void conv_gemm(
    const float* __restrict__ Wp, const float* __restrict__ bp, int layer)
{
    __shared__ float As[BK][BM + 8];   // [k][m], pad -> conflict-free frag loads
    __shared__ float Bsm[BK][BN + 8];  // [k][n]
    int tid = threadIdx.x;
    int warp = tid >> 5, lane = tid & 31;
    int grp = lane >> 2, tq = lane & 3;
    int m0 = blockIdx.y * BM, n0 = blockIdx.x * BN;
    int batch = blockIdx.z;
    const float* A  = Wp + (size_t)layer * 2 * H * H;
    const float* Bg = g_Y + (size_t)batch * H * LSEQ;
    int wm = (warp >> 1) * 32, wn = (warp & 1) * 32;

    float acc[2][4][4];
#pragma unroll
    for (int mi = 0; mi < 2; mi++)
#pragma unroll
        for (int ni = 0; ni < 4; ni++)
#pragma unroll
            for (int r = 0; r < 4; r++) acc[mi][ni][r] = 0.0f;

    for (int kk = 0; kk < H; kk += BK) {
#pragma unroll
        for (int i = 0; i < 2; i++) {
            int idx = i * 256 + tid;
            int m = idx >> 2, k4 = (idx & 3) * 4;
            float4 v = *(const float4*)(A + (size_t)(m0 + m) * H + kk + k4);
            As[k4 + 0][m] = v.x; As[k4 + 1][m] = v.y;
            As[k4 + 2][m] = v.z; As[k4 + 3][m] = v.w;
        }
        {
            int k = tid >> 4, l4 = (tid & 15) * 4;
            float4 v = *(const float4*)(Bg + (size_t)(kk + k) * LSEQ + n0 + l4);
            *(float4*)&Bsm[k][l4] = v;
        }
        __syncthreads();
#pragma unroll
        for (int ks = 0; ks < BK; ks += 8) {
            unsigned ahi[2][4], alo[2][4];
#pragma unroll
            for (int mi = 0; mi < 2; mi++) {
                int mb = wm + mi * 16;
                float f[4];
                f[0] = As[ks + tq][mb + grp];
                f[1] = As[ks + tq][mb + grp + 8];
                f[2] = As[ks + tq + 4][mb + grp];
                f[3] = As[ks + tq + 4][mb + grp + 8];
#pragma unroll
                for (int r = 0; r < 4; r++) {
                    unsigned hb = f2tf32(f[r]);
                    ahi[mi][r] = hb;
                    alo[mi][r] = f2tf32(f[r] - __uint_as_float(hb));
                }
            }
            unsigned bhi[4][2], blo[4][2];
#pragma unroll
            for (int ni = 0; ni < 4; ni++) {
                int nb = wn + ni * 8 + grp;
                float g0 = Bsm[ks + tq][nb];
                float g1 = Bsm[ks + tq + 4][nb];
                unsigned h0b = f2tf32(g0), h1b = f2tf32(g1);
                bhi[ni][0] = h0b; bhi[ni][1] = h1b;
                blo[ni][0] = f2tf32(g0 - __uint_as_float(h0b));
                blo[ni][1] = f2tf32(g1 - __uint_as_float(h1b));
            }
#pragma unroll
            for (int mi = 0; mi < 2; mi++)
#pragma unroll
                for (int ni = 0; ni < 4; ni++) {
                    mma_tf32(acc[mi][ni], ahi[mi], bhi[ni]);
                    mma_tf32(acc[mi][ni], alo[mi], bhi[ni]);
                    mma_tf32(acc[mi][ni], ahi[mi], blo[ni]);
                }
        }
        __syncthreads();
    }
    // epilogue: + bias, store Z
#pragma unroll
    for (int mi = 0; mi < 2; mi++)
#pragma unroll
        for (int ni = 0; ni < 4; ni++) {
            int r0 = m0 + wm + mi * 16 + grp;
            int cc = n0 + wn + ni * 8 + tq * 2;
            float b0v = bp[layer * 2 * H + r0];
            float b1v = bp[layer * 2 * H + r0 + 8];
            float2 v0 = {acc[mi][ni][0] + b0v, acc[mi][ni][1] + b0v};
            float2 v1 = {acc[mi][ni][2] + b1v, acc[mi][ni][3] + b1v};
            *(float2*)&g_Z[((size_t)batch * 2 * H + r0) * LSEQ + cc] = v0;
            *(float2*)&g_Z[((size_t)batch * 2 * H + r0 + 8) * LSEQ + cc] = v1;
        }
}

// ================= GLU + residual + LayerNorm (over h, layout (B,H,L)) ======
#define TL 64
__global__ __launch_bounds__(256) void glu_ln(
    const float* __restrict__ gamma, const float* __restrict__ beta,
    int layer, int ping)
{
    extern __shared__ float sv[];     // H*TL floats = 128KB
    __shared__ float ps[4 * TL], ps2[4 * TL], smu[TL], srs[TL];
    const float* xin = ping ? g_xB : g_xA;
    float* xout = ping ? g_xA : g_xB;
    int b = blockIdx.y;
    int l0 = blockIdx.x * TL;
    int tid = threadIdx.x;
    const float* Za = g_Z + (size_t)b * 2 * H * LSEQ;

    for (int idx = tid; idx < H * TL; idx += 256) {
        int hh = idx >> 6, ll = idx & 63;
        float a = Za[(size_t)hh * LSEQ + l0 + ll];
        float g = Za[(size_t)(hh + H) * LSEQ + l0 + ll];
        float xv = xin[((size_t)b * H + hh) * LSEQ + l0 + ll];
        float v = a * (1.0f / (1.0f + expf(-g))) + xv;
        sv[idx] = v;
    }
    __syncthreads();
    {
        int hp = tid >> 6, ll = tid & 63;
        float s = 0.f, s2 = 0.f;
        for (int hh = hp * 128; hh < hp * 128 + 128; hh++) {
            float v = sv[hh * TL + ll];
            s += v; s2 = fmaf(v, v, s2);
        }
        ps[tid] = s; ps2[tid] = s2;
    }
    __syncthreads();
    if (tid < TL) {
        float s  = ps[tid] + ps[TL + tid] + ps[2 * TL + tid] + ps[3 * TL + tid];
        float s2 = ps2[tid] + ps2[TL + tid] + ps2[2 * TL + tid] + ps2[3 * TL + tid];
        float mu = s * (1.0f / H);
        float var = s2 * (1.0f / H) - mu * mu;
        smu[tid] = mu;
        srs[tid] = rsqrtf(var + LN_EPS);
    }
    __syncthreads();
    for (int idx = tid; idx < H * TL; idx += 256) {
        int hh = idx >> 6, ll = idx & 63;
        float v = (sv[idx] - smu[ll]) * srs[ll] * gamma[layer * H + hh]
                  + beta[layer * H + hh];
        xout[((size_t)b * H + hh) * LSEQ + l0 + ll] = v;
    }
}

// ================= launcher =================
extern "C" void kernel_launch(void* const* d_in, const int* in_sizes, int n_in,
                              void* d_out, int out_size)
{
    const float* x          = (const float*)d_in[0];
    const float* log_dt     = (const float*)d_in[1];
    const float* A_imag     = (const float*)d_in[2];
    const float* log_A_real = (const float*)d_in[3];
    const float* C          = (const float*)d_in[4];
    const float* D          = (const float*)d_in[5];
    const float* W          = (const float*)d_in[6];
    const float* bconv      = (const float*)d_in[7];
    const float* gamma      = (const float*)d_in[8];
    const float* beta       = (const float*)d_in[9];
    float* out = (float*)d_out;

    const int glu_smem = H * TL * sizeof(float);   // 131072
    cudaFuncSetAttribute(glu_ln, cudaFuncAttributeMaxDynamicSharedMemorySize, glu_smem);

    dim3 tb(32, 8);
    transpose_in<<<dim3(H / 32, LSEQ / 32, BSZ), tb>>>(x);

    int ping = 0;
    for (int i = 0; i < NLAY; i++) {
        ssm_scan<<<(BSZ * H * 8) / 128, 128>>>(log_dt, A_imag, log_A_real, C, D, i, ping);
        conv_gemm<<<dim3(LSEQ / BN, 2 * H / BM, BSZ), 256>>>(W, bconv, i);
        glu_ln<<<dim3(LSEQ / TL, BSZ), 256, glu_smem>>>(gamma, beta, i, ping);
        ping ^= 1;
    }
    transpose_out<<<dim3(LSEQ / 32, H / 32, BSZ), tb>>>(out, ping);
}

// round 2
// speedup vs baseline: 1.0068x; 1.0068x over previous
#include <cuda_runtime.h>
#include <cstdint>

#define H    512
#define NLAY 4
#define N2   32
#define BSZ  8
#define LSEQ 4096
#define LN_EPS 1e-5f

// ---- static scratch (allocation-free rule) ----
__device__ float g_xA[(size_t)BSZ * H * LSEQ];      // 64MB  activations (B,H,L)
__device__ float g_xB[(size_t)BSZ * H * LSEQ];      // 64MB  ping-pong
__device__ float g_Y [(size_t)BSZ * H * LSEQ];      // 64MB  gelu(ssm out)
__device__ float g_Z [(size_t)BSZ * 2 * H * LSEQ];  // 128MB conv output

// ================= transpose (B,L,H) -> (B,H,L) =================
__global__ void transpose_in(const float* __restrict__ x) {
    __shared__ float tile[32][33];
    int b = blockIdx.z;
    int h0 = blockIdx.x * 32, l0 = blockIdx.y * 32;
    int tx = threadIdx.x, ty = threadIdx.y;
#pragma unroll
    for (int j = 0; j < 32; j += 8)
        tile[ty + j][tx] = x[((size_t)b * LSEQ + (l0 + ty + j)) * H + h0 + tx];
    __syncthreads();
#pragma unroll
    for (int j = 0; j < 32; j += 8)
        g_xA[((size_t)b * H + (h0 + ty + j)) * LSEQ + l0 + tx] = tile[tx][ty + j];
}

// ================= transpose (B,H,L) -> (B,L,H) =================
__global__ void transpose_out(float* __restrict__ out, int ping) {
    const float* xin = ping ? g_xB : g_xA;
    __shared__ float tile[32][33];
    int b = blockIdx.z;
    int l0 = blockIdx.x * 32, h0 = blockIdx.y * 32;
    int tx = threadIdx.x, ty = threadIdx.y;
#pragma unroll
    for (int j = 0; j < 32; j += 8)
        tile[ty + j][tx] = xin[((size_t)b * H + (h0 + ty + j)) * LSEQ + l0 + tx];
    __syncthreads();
#pragma unroll
    for (int j = 0; j < 32; j += 8)
        out[((size_t)b * LSEQ + (l0 + tx)) * H + h0 + ty + j] = tile[ty + j][tx];
}

// ================= SSM scan: 8 lanes per (b,h), 4 complex states/lane ========
__global__ __launch_bounds__(128) void ssm_scan(
    const float* __restrict__ log_dt, const float* __restrict__ A_imag,
    const float* __restrict__ log_A_real, const float* __restrict__ Cp,
    const float* __restrict__ Dp, int layer, int ping)
{
    const float* xin = ping ? g_xB : g_xA;
    int tid = blockIdx.x * blockDim.x + threadIdx.x;
    int group = tid >> 3;        // 0 .. B*H-1
    int li = tid & 7;            // lane in group
    int lane = threadIdx.x & 31;
    int h = group & (H - 1);

    float dt = expf(log_dt[layer * H + h]);
    int pbase = (layer * H + h) * N2 + li * 4;
    float4 aim = *(const float4*)(A_imag + pbase);
    float4 lar = *(const float4*)(log_A_real + pbase);
    float4 c01 = *(const float4*)(Cp + 2 * pbase);
    float4 c23 = *(const float4*)(Cp + 2 * pbase + 4);
    float aimv[4] = {aim.x, aim.y, aim.z, aim.w};
    float larv[4] = {lar.x, lar.y, lar.z, lar.w};
    float ccr[4]  = {c01.x, c01.z, c23.x, c23.z};
    float cci[4]  = {c01.y, c01.w, c23.y, c23.w};

    float w_re[4], w_im[4], cf_re[4], cf_im[4];
#pragma unroll
    for (int j = 0; j < 4; j++) {
        float Are = -expf(larv[j]);
        float Aim = aimv[j];
        float dre = Are * dt, dim = Aim * dt;
        float e = expf(dre);
        float wr = e * cosf(dim), wi = e * sinf(dim);
        w_re[j] = wr; w_im[j] = wi;
        float nr = wr - 1.0f, ni = wi;                 // exp(dA)-1
        float tr = ccr[j] * nr - cci[j] * ni;          // C*(exp(dA)-1)
        float ti = ccr[j] * ni + cci[j] * nr;
        float inv = 2.0f / (Are * Are + Aim * Aim);    // fold the "2*Re" factor
        cf_re[j] = (tr * Are + ti * Aim) * inv;        // * conj(A)/|A|^2
        cf_im[j] = (ti * Are - tr * Aim) * inv;
    }
    float Dh = Dp[layer * H + h];

    const float* urow = xin + (size_t)group * LSEQ;
    float* yrow = g_Y + (size_t)group * LSEQ;

    float sre[4] = {0.f, 0.f, 0.f, 0.f}, sim[4] = {0.f, 0.f, 0.f, 0.f};
    float ucur = urow[li];
    for (int l0 = 0; l0 < LSEQ; l0 += 8) {
        float unext = (l0 + 8 < LSEQ) ? urow[l0 + 8 + li] : 0.0f;
        float yl = 0.0f;
#pragma unroll
        for (int k = 0; k < 8; k++) {
            float u = __shfl_sync(0xffffffffu, ucur, (lane & 24) | k);
            float c = 0.0f;
#pragma unroll
            for (int j = 0; j < 4; j++) {
                float tim = fmaf(w_im[j], sre[j], w_re[j] * sim[j]);
                float tre = fmaf(w_re[j], sre[j], u);
                tre = fmaf(-w_im[j], sim[j], tre);
                sre[j] = tre; sim[j] = tim;
                c = fmaf(cf_re[j], tre, c);
                c = fmaf(-cf_im[j], tim, c);
            }
            c += __shfl_xor_sync(0xffffffffu, c, 1);
            c += __shfl_xor_sync(0xffffffffu, c, 2);
            c += __shfl_xor_sync(0xffffffffu, c, 4);
            if (k == li) yl = fmaf(Dh, u, c);
        }
        // exact GELU (erf form), coalesced 32B store per group
        float gl = 0.5f * yl * (1.0f + erff(yl * 0.70710678118654752f));
        yrow[l0 + li] = gl;
        ucur = unext;
    }
}

// ================= 1x1 conv GEMM: Z = W @ Y  (split-tf32, fp32 accuracy) ====
#define BM 128
#define BN 64
#define BK 16

__device__ __forceinline__ unsigned f2tf32(float x) {
    unsigned r;
    asm("cvt.rna.tf32.f32 %0, %1;" : "=r"(r) : "f"(x));
    return r;
}
__device__ __forceinline__ void mma_tf32(float* d, const unsigned* a, const unsigned* bf) {
    asm volatile(
        "mma.sync.aligned.m16n8k8.row.col.f32.tf32.tf32.f32 "
        "{%0,%1,%2,%3}, {%4,%5,%6,%7}, {%8,%9}, {%0,%1,%2,%3};"
        : "+f"(d[0]), "+f"(d[1]), "+f"(d[2]), "+f"(d[3])
        : "r"(a[0]), "r"(a[1]), "r"(a[2]), "r"(a[3]), "r"(bf[0]), "r"(bf[1]));
}

__global__ __launch_bounds__(256) void conv_gemm(
    const float* __restrict__ Wp, const float* __restrict__ bp, int layer)
{
    __shared__ float As[BK][BM + 8];   // [k][m], pad -> conflict-free frag loads
    __shared__ float Bsm[BK][BN + 8];  // [k][n]
    int tid = threadIdx.x;
    int warp = tid >> 5, lane = tid & 31;
    int grp = lane >> 2, tq = lane & 3;
    int m0 = blockIdx.y * BM, n0 = blockIdx.x * BN;
    int batch = blockIdx.z;
    const float* A  = Wp + (size_t)layer * 2 * H * H;
    const float* Bg = g_Y + (size_t)batch * H * LSEQ;
    int wm = (warp >> 1) * 32, wn = (warp & 1) * 32;

    float acc[2][4][4];
#pragma unroll
    for (int mi = 0; mi < 2; mi++)
#pragma unroll
        for (int ni = 0; ni < 4; ni++)
#pragma unroll
            for (int r = 0; r < 4; r++) acc[mi][ni][r] = 0.0f;

    for (int kk = 0; kk < H; kk += BK) {
#pragma unroll
        for (int i = 0; i < 2; i++) {
            int idx = i * 256 + tid;
            int m = idx >> 2, k4 = (idx & 3) * 4;
            float4 v = *(const float4*)(A + (size_t)(m0 + m) * H + kk + k4);
            As[k4 + 0][m] = v.x; As[k4 + 1][m] = v.y;
            As[k4 + 2][m] = v.z; As[k4 + 3][m] = v.w;
        }
        {
            int k = tid >> 4, l4 = (tid & 15) * 4;
            float4 v = *(const float4*)(Bg + (size_t)(kk + k) * LSEQ + n0 + l4);
            *(float4*)&Bsm[k][l4] = v;
        }
        __syncthreads();
#pragma unroll
        for (int ks = 0; ks < BK; ks += 8) {
            unsigned ahi[2][4], alo[2][4];
#pragma unroll
            for (int mi = 0; mi < 2; mi++) {
                int mb = wm + mi * 16;
                float f[4];
                f[0] = As[ks + tq][mb + grp];
                f[1] = As[ks + tq][mb + grp + 8];
                f[2] = As[ks + tq + 4][mb + grp];
                f[3] = As[ks + tq + 4][mb + grp + 8];
#pragma unroll
                for (int r = 0; r < 4; r++) {
                    unsigned hb = f2tf32(f[r]);
                    ahi[mi][r] = hb;
                    alo[mi][r] = f2tf32(f[r] - __uint_as_float(hb));
                }
            }
            unsigned bhi[4][2], blo[4][2];
#pragma unroll
            for (int ni = 0; ni < 4; ni++) {
                int nb = wn + ni * 8 + grp;
                float g0 = Bsm[ks + tq][nb];
                float g1 = Bsm[ks + tq + 4][nb];
                unsigned h0b = f2tf32(g0), h1b = f2tf32(g1);
                bhi[ni][0] = h0b; bhi[ni][1] = h1b;
                blo[ni][0] = f2tf32(g0 - __uint_as_float(h0b));
                blo[ni][1] = f2tf32(g1 - __uint_as_float(h1b));
            }
#pragma unroll
            for (int mi = 0; mi < 2; mi++)
#pragma unroll
                for (int ni = 0; ni < 4; ni++) {
                    mma_tf32(acc[mi][ni], ahi[mi], bhi[ni]);
                    mma_tf32(acc[mi][ni], alo[mi], bhi[ni]);
                    mma_tf32(acc[mi][ni], ahi[mi], blo[ni]);
                }
        }
        __syncthreads();
    }
    // epilogue: + bias, store Z
#pragma unroll
    for (int mi = 0; mi < 2; mi++)
#pragma unroll
        for (int ni = 0; ni < 4; ni++) {
            int r0 = m0 + wm + mi * 16 + grp;
            int cc = n0 + wn + ni * 8 + tq * 2;
            float b0v = bp[layer * 2 * H + r0];
            float b1v = bp[layer * 2 * H + r0 + 8];
            float2 v0 = {acc[mi][ni][0] + b0v, acc[mi][ni][1] + b0v};
            float2 v1 = {acc[mi][ni][2] + b1v, acc[mi][ni][3] + b1v};
            *(float2*)&g_Z[((size_t)batch * 2 * H + r0) * LSEQ + cc] = v0;
            *(float2*)&g_Z[((size_t)batch * 2 * H + r0 + 8) * LSEQ + cc] = v1;
        }
}

// ================= GLU + residual + LayerNorm (over h, layout (B,H,L)) ======
#define TL 64
__global__ __launch_bounds__(256) void glu_ln(
    const float* __restrict__ gamma, const float* __restrict__ beta,
    int layer, int ping)
{
    extern __shared__ float sv[];     // H*TL floats = 128KB
    __shared__ float ps[4 * TL], ps2[4 * TL], smu[TL], srs[TL];
    const float* xin = ping ? g_xB : g_xA;
    float* xout = ping ? g_xA : g_xB;
    int b = blockIdx.y;
    int l0 = blockIdx.x * TL;
    int tid = threadIdx.x;
    const float* Za = g_Z + (size_t)b * 2 * H * LSEQ;

    for (int idx = tid; idx < H * TL; idx += 256) {
        int hh = idx >> 6, ll = idx & 63;
        float a = Za[(size_t)hh * LSEQ + l0 + ll];
        float g = Za[(size_t)(hh + H) * LSEQ + l0 + ll];
        float xv = xin[((size_t)b * H + hh) * LSEQ + l0 + ll];
        float v = a * (1.0f / (1.0f + expf(-g))) + xv;
        sv[idx] = v;
    }
    __syncthreads();
    {
        int hp = tid >> 6, ll = tid & 63;
        float s = 0.f, s2 = 0.f;
        for (int hh = hp * 128; hh < hp * 128 + 128; hh++) {
            float v = sv[hh * TL + ll];
            s += v; s2 = fmaf(v, v, s2);
        }
        ps[tid] = s; ps2[tid] = s2;
    }
    __syncthreads();
    if (tid < TL) {
        float s  = ps[tid] + ps[TL + tid] + ps[2 * TL + tid] + ps[3 * TL + tid];
        float s2 = ps2[tid] + ps2[TL + tid] + ps2[2 * TL + tid] + ps2[3 * TL + tid];
        float mu = s * (1.0f / H);
        float var = s2 * (1.0f / H) - mu * mu;
        smu[tid] = mu;
        srs[tid] = rsqrtf(var + LN_EPS);
    }
    __syncthreads();
    for (int idx = tid; idx < H * TL; idx += 256) {
        int hh = idx >> 6, ll = idx & 63;
        float v = (sv[idx] - smu[ll]) * srs[ll] * gamma[layer * H + hh]
                  + beta[layer * H + hh];
        xout[((size_t)b * H + hh) * LSEQ + l0 + ll] = v;
    }
}

// ================= launcher =================
extern "C" void kernel_launch(void* const* d_in, const int* in_sizes, int n_in,
                              void* d_out, int out_size)
{
    const float* x          = (const float*)d_in[0];
    const float* log_dt     = (const float*)d_in[1];
    const float* A_imag     = (const float*)d_in[2];
    const float* log_A_real = (const float*)d_in[3];
    const float* C          = (const float*)d_in[4];
    const float* D          = (const float*)d_in[5];
    const float* W          = (const float*)d_in[6];
    const float* bconv      = (const float*)d_in[7];
    const float* gamma      = (const float*)d_in[8];
    const float* beta       = (const float*)d_in[9];
    float* out = (float*)d_out;

    const int glu_smem = H * TL * sizeof(float);   // 131072
    cudaFuncSetAttribute(glu_ln, cudaFuncAttributeMaxDynamicSharedMemorySize, glu_smem);

    dim3 tb(32, 8);
    transpose_in<<<dim3(H / 32, LSEQ / 32, BSZ), tb>>>(x);

    int ping = 0;
    for (int i = 0; i < NLAY; i++) {
        ssm_scan<<<(BSZ * H * 8) / 128, 128>>>(log_dt, A_imag, log_A_real, C, D, i, ping);
        conv_gemm<<<dim3(LSEQ / BN, 2 * H / BM, BSZ), 256>>>(W, bconv, i);
        glu_ln<<<dim3(LSEQ / TL, BSZ), 256, glu_smem>>>(gamma, beta, i, ping);
        ping ^= 1;
    }
    transpose_out<<<dim3(LSEQ / 32, H / 32, BSZ), tb>>>(out, ping);
}

// round 3
// speedup vs baseline: 1.6782x; 1.6669x over previous
#include <cuda_runtime.h>
#include <cstdint>

#define H    512
#define NLAY 4
#define N2   32
#define BSZ  8
#define LSEQ 4096
#define MROWS (BSZ * LSEQ)     /* 32768 */
#define LN_EPS 1e-5f

typedef unsigned long long u64;

// ---- static scratch (allocation-free rule). layout (B,L,H) row-major ----
__device__ float g_xA[(size_t)MROWS * H];        // 64MB
__device__ float g_xB[(size_t)MROWS * H];        // 64MB
__device__ float g_Y [(size_t)MROWS * H];        // 64MB  gelu(ssm out)
__device__ float g_Z [(size_t)MROWS * 2 * H];    // 128MB conv output

// ---------------- packed f32x2 helpers ----------------
__device__ __forceinline__ u64 pk(float lo, float hi) {
    u64 r; asm("mov.b64 %0, {%1,%2};" : "=l"(r) : "f"(lo), "f"(hi)); return r;
}
__device__ __forceinline__ void upk(u64 v, float& lo, float& hi) {
    asm("mov.b64 {%0,%1}, %2;" : "=f"(lo), "=f"(hi) : "l"(v));
}
__device__ __forceinline__ u64 fma2(u64 a, u64 b, u64 c) {
    u64 d; asm("fma.rn.f32x2 %0, %1, %2, %3;" : "=l"(d) : "l"(a), "l"(b), "l"(c)); return d;
}
__device__ __forceinline__ u64 mul2(u64 a, u64 b) {
    u64 d; asm("mul.rn.f32x2 %0, %1, %2;" : "=l"(d) : "l"(a), "l"(b)); return d;
}

// =====================================================================
// SSM scan + GELU.  grid = BSZ * (H/32) = 128 blocks, 256 threads.
// Block handles 32 h-channels of one batch over full L.
// 8 lanes per h, 4 complex states per lane, states packed 2-wide (f32x2).
// u and y staged through smem tiles (16 steps), double-buffered.
// =====================================================================
__global__ __launch_bounds__(256) void ssm_scan(
    const float* __restrict__ xin,
    const float* __restrict__ log_dt, const float* __restrict__ A_imag,
    const float* __restrict__ log_A_real, const float* __restrict__ Cp,
    const float* __restrict__ Dp, int layer)
{
    __shared__ float u_t[2][16][32];
    __shared__ float y_t[2][16][32];

    int tid  = threadIdx.x;
    int b    = blockIdx.x >> 4;
    int h0   = (blockIdx.x & 15) * 32;
    int hloc = tid >> 3;
    int li   = tid & 7;
    int h    = h0 + hloc;
    int lrow = tid >> 5;      // 0..7  (cooperative tile row)
    int lcol = tid & 31;      // 0..31 (cooperative tile col)

    // ---- per-(h, lane) coefficients (verified math from round 1) ----
    float dt = expf(log_dt[layer * H + h]);
    int pbase = (layer * H + h) * N2 + li * 4;
    float4 aim = *(const float4*)(A_imag + pbase);
    float4 lar = *(const float4*)(log_A_real + pbase);
    float4 c01 = *(const float4*)(Cp + 2 * pbase);
    float4 c23 = *(const float4*)(Cp + 2 * pbase + 4);
    float aimv[4] = {aim.x, aim.y, aim.z, aim.w};
    float larv[4] = {lar.x, lar.y, lar.z, lar.w};
    float ccr[4]  = {c01.x, c01.z, c23.x, c23.z};
    float cci[4]  = {c01.y, c01.w, c23.y, c23.w};

    float w_re[4], w_im[4], cf_re[4], cf_im[4];
#pragma unroll
    for (int j = 0; j < 4; j++) {
        float Are = -expf(larv[j]);
        float Aim = aimv[j];
        float e = expf(Are * dt);
        float wr = e * cosf(Aim * dt), wi = e * sinf(Aim * dt);
        w_re[j] = wr; w_im[j] = wi;
        float nr = wr - 1.0f, ni = wi;
        float tr = ccr[j] * nr - cci[j] * ni;
        float ti = ccr[j] * ni + cci[j] * nr;
        float inv = 2.0f / (Are * Are + Aim * Aim);
        cf_re[j] = (tr * Are + ti * Aim) * inv;
        cf_im[j] = (ti * Are - tr * Aim) * inv;
    }
    u64 w2re[2]  = {pk(w_re[0], w_re[1]),  pk(w_re[2], w_re[3])};
    u64 w2im[2]  = {pk(w_im[0], w_im[1]),  pk(w_im[2], w_im[3])};
    u64 nw2im[2] = {pk(-w_im[0], -w_im[1]), pk(-w_im[2], -w_im[3])};
    u64 cf2re[2] = {pk(cf_re[0], cf_re[1]), pk(cf_re[2], cf_re[3])};
    u64 ncf2im[2]= {pk(-cf_im[0], -cf_im[1]), pk(-cf_im[2], -cf_im[3])};
    float Dh = Dp[layer * H + h];

    const float* xr = xin + (size_t)b * LSEQ * H + h0;
    float*       yr = g_Y + (size_t)b * LSEQ * H + h0;

    // prologue: load tile 0 (coalesced, 128B rows)
    u_t[0][lrow][lcol]     = xr[(size_t)lrow * H + lcol];
    u_t[0][lrow + 8][lcol] = xr[(size_t)(lrow + 8) * H + lcol];
    __syncthreads();

    u64 s2re[2] = {0ull, 0ull}, s2im[2] = {0ull, 0ull};

    for (int it = 0; it < LSEQ / 16; it++) {
        int buf = it & 1;
        int l0 = it * 16;
        float p0 = 0.0f, p1 = 0.0f;
        if (it + 1 < LSEQ / 16) {
            p0 = xr[(size_t)(l0 + 16 + lrow) * H + lcol];
            p1 = xr[(size_t)(l0 + 24 + lrow) * H + lcol];
        }
        float yl0 = 0.0f, yl1 = 0.0f;
#pragma unroll
        for (int k = 0; k < 16; k++) {
            float u = u_t[buf][k][hloc];
            u64 u2 = pk(u, u);
            u64 nre0 = fma2(w2re[0], s2re[0], fma2(nw2im[0], s2im[0], u2));
            u64 nim0 = fma2(w2im[0], s2re[0], mul2(w2re[0], s2im[0]));
            s2re[0] = nre0; s2im[0] = nim0;
            u64 c2 = mul2(cf2re[0], nre0);
            c2 = fma2(ncf2im[0], nim0, c2);
            u64 nre1 = fma2(w2re[1], s2re[1], fma2(nw2im[1], s2im[1], u2));
            u64 nim1 = fma2(w2im[1], s2re[1], mul2(w2re[1], s2im[1]));
            s2re[1] = nre1; s2im[1] = nim1;
            c2 = fma2(cf2re[1], nre1, c2);
            c2 = fma2(ncf2im[1], nim1, c2);
            float clo, chi; upk(c2, clo, chi);
            float c = clo + chi;
            c += __shfl_xor_sync(0xffffffffu, c, 1);
            c += __shfl_xor_sync(0xffffffffu, c, 2);
            c += __shfl_xor_sync(0xffffffffu, c, 4);
            c = fmaf(Dh, u, c);
            if ((k & 7) == li) { if (k < 8) yl0 = c; else yl1 = c; }
        }
        // exact GELU (erf form)
        yl0 = 0.5f * yl0 * (1.0f + erff(yl0 * 0.70710678118654752f));
        yl1 = 0.5f * yl1 * (1.0f + erff(yl1 * 0.70710678118654752f));
        y_t[buf][li][hloc] = yl0;
        y_t[buf][li + 8][hloc] = yl1;
        if (it + 1 < LSEQ / 16) {
            u_t[buf ^ 1][lrow][lcol] = p0;
            u_t[buf ^ 1][lrow + 8][lcol] = p1;
        }
        __syncthreads();
        // coalesced y store
        yr[(size_t)(l0 + lrow) * H + lcol]     = y_t[buf][lrow][lcol];
        yr[(size_t)(l0 + lrow + 8) * H + lcol] = y_t[buf][lrow + 8][lcol];
    }
}

// =====================================================================
// GEMM: Z[M=32768, N=1024] = Y[M, K=512] @ W^T   (W is [1024, 512])
// split-tf32 (3 mma per product) for fp32 accuracy; cp.async 2-stage.
// =====================================================================
#define GBM 128
#define GBN 128
#define GBK 16
#define NKIT (H / GBK)   /* 32 */

__device__ __forceinline__ unsigned f2tf32(float x) {
    unsigned r; asm("cvt.rna.tf32.f32 %0, %1;" : "=r"(r) : "f"(x)); return r;
}
__device__ __forceinline__ void mma8(float* d, const unsigned* a, const unsigned* b) {
    asm volatile(
        "mma.sync.aligned.m16n8k8.row.col.f32.tf32.tf32.f32 "
        "{%0,%1,%2,%3}, {%4,%5,%6,%7}, {%8,%9}, {%0,%1,%2,%3};"
        : "+f"(d[0]), "+f"(d[1]), "+f"(d[2]), "+f"(d[3])
        : "r"(a[0]), "r"(a[1]), "r"(a[2]), "r"(a[3]), "r"(b[0]), "r"(b[1]));
}

__global__ __launch_bounds__(256, 2) void conv_gemm(
    const float* __restrict__ Wp, const float* __restrict__ bp, int layer)
{
    __shared__ float As[2][GBM][20];   // [m][k], stride 20 -> conflict-free
    __shared__ float Bs[2][GBN][20];   // [n][k]
    __shared__ float bias_s[GBN];

    int tid = threadIdx.x;
    int warp = tid >> 5, lane = tid & 31;
    int grp = lane >> 2, tq = lane & 3;
    int m0 = blockIdx.y * GBM;
    int n0 = blockIdx.x * GBN;
    const float* Am = g_Y;
    const float* Bm = Wp + (size_t)layer * 2 * H * H;
    if (tid < GBN) bias_s[tid] = bp[layer * 2 * H + n0 + tid];

    int wm = (warp >> 1) * 32, wn = (warp & 1) * 64;
    float acc[2][8][4];
#pragma unroll
    for (int mi = 0; mi < 2; mi++)
#pragma unroll
        for (int ni = 0; ni < 8; ni++)
#pragma unroll
            for (int r = 0; r < 4; r++) acc[mi][ni][r] = 0.0f;

    int cm = tid >> 2, ck4 = (tid & 3) << 2;       // chunk 0 mapping
    int cm2 = (tid + 256) >> 2;                    // chunk 1 row (same ck4)

#define LOAD_STAGE(KK, BUF)                                                      \
    do {                                                                         \
        const float* ga0 = Am + (size_t)(m0 + cm)  * H + (KK) + ck4;             \
        const float* ga1 = Am + (size_t)(m0 + cm2) * H + (KK) + ck4;             \
        unsigned sa0 = (unsigned)__cvta_generic_to_shared(&As[BUF][cm][ck4]);    \
        unsigned sa1 = (unsigned)__cvta_generic_to_shared(&As[BUF][cm2][ck4]);   \
        asm volatile("cp.async.cg.shared.global [%0], [%1], 16;\n" ::"r"(sa0), "l"(ga0)); \
        asm volatile("cp.async.cg.shared.global [%0], [%1], 16;\n" ::"r"(sa1), "l"(ga1)); \
        const float* gb0 = Bm + (size_t)(n0 + cm)  * H + (KK) + ck4;             \
        const float* gb1 = Bm + (size_t)(n0 + cm2) * H + (KK) + ck4;             \
        unsigned sb0 = (unsigned)__cvta_generic_to_shared(&Bs[BUF][cm][ck4]);    \
        unsigned sb1 = (unsigned)__cvta_generic_to_shared(&Bs[BUF][cm2][ck4]);   \
        asm volatile("cp.async.cg.shared.global [%0], [%1], 16;\n" ::"r"(sb0), "l"(gb0)); \
        asm volatile("cp.async.cg.shared.global [%0], [%1], 16;\n" ::"r"(sb1), "l"(gb1)); \
        asm volatile("cp.async.commit_group;\n");                                \
    } while (0)

    LOAD_STAGE(0, 0);

    for (int kt = 0; kt < NKIT; kt++) {
        int buf = kt & 1;
        if (kt + 1 < NKIT) {
            LOAD_STAGE((kt + 1) * GBK, buf ^ 1);
            asm volatile("cp.async.wait_group 1;\n");
        } else {
            asm volatile("cp.async.wait_group 0;\n");
        }
        __syncthreads();
#pragma unroll
        for (int ks = 0; ks < GBK; ks += 8) {
            unsigned ahi[2][4], alo[2][4];
#pragma unroll
            for (int mi = 0; mi < 2; mi++) {
                int mb = wm + mi * 16;
                float f[4];
                f[0] = As[buf][mb + grp][ks + tq];
                f[1] = As[buf][mb + grp + 8][ks + tq];
                f[2] = As[buf][mb + grp][ks + tq + 4];
                f[3] = As[buf][mb + grp + 8][ks + tq + 4];
#pragma unroll
                for (int r = 0; r < 4; r++) {
                    unsigned hb = f2tf32(f[r]);
                    ahi[mi][r] = hb;
                    alo[mi][r] = f2tf32(f[r] - __uint_as_float(hb));
                }
            }
#pragma unroll
            for (int ni = 0; ni < 8; ni++) {
                int nb = wn + ni * 8 + grp;
                float g0 = Bs[buf][nb][ks + tq];
                float g1 = Bs[buf][nb][ks + tq + 4];
                unsigned bhi[2], blo[2];
                bhi[0] = f2tf32(g0); bhi[1] = f2tf32(g1);
                blo[0] = f2tf32(g0 - __uint_as_float(bhi[0]));
                blo[1] = f2tf32(g1 - __uint_as_float(bhi[1]));
#pragma unroll
                for (int mi = 0; mi < 2; mi++) {
                    mma8(acc[mi][ni], ahi[mi], bhi);
                    mma8(acc[mi][ni], alo[mi], bhi);
                    mma8(acc[mi][ni], ahi[mi], blo);
                }
            }
        }
        __syncthreads();
    }

    // epilogue: bias + store (Z row-major, cols contiguous)
#pragma unroll
    for (int mi = 0; mi < 2; mi++)
#pragma unroll
        for (int ni = 0; ni < 8; ni++) {
            int r  = m0 + wm + mi * 16 + grp;
            int cb = wn + ni * 8 + tq * 2;
            float b0 = bias_s[cb], b1 = bias_s[cb + 1];
            float2 v0 = {acc[mi][ni][0] + b0, acc[mi][ni][1] + b1};
            float2 v1 = {acc[mi][ni][2] + b0, acc[mi][ni][3] + b1};
            *(float2*)&g_Z[(size_t)r * (2 * H) + n0 + cb] = v0;
            *(float2*)&g_Z[(size_t)(r + 8) * (2 * H) + n0 + cb] = v1;
        }
}

// =====================================================================
// GLU + residual + LayerNorm. warp per row (512 contiguous floats).
// =====================================================================
__global__ __launch_bounds__(128) void glu_ln(
    const float* __restrict__ xin, float* __restrict__ xout,
    const float* __restrict__ gamma, const float* __restrict__ beta, int layer)
{
    int row  = blockIdx.x * 4 + (threadIdx.x >> 5);
    int lane = threadIdx.x & 31;
    const float4* z4 = (const float4*)(g_Z + (size_t)row * (2 * H));
    const float4* x4 = (const float4*)(xin + (size_t)row * H);
    float4* o4       = (float4*)(xout + (size_t)row * H);
    const float4* g4 = (const float4*)(gamma + layer * H);
    const float4* e4 = (const float4*)(beta + layer * H);

    float4 v[4];
    float s = 0.0f, s2 = 0.0f;
#pragma unroll
    for (int j = 0; j < 4; j++) {
        float4 a  = z4[j * 32 + lane];
        float4 g  = z4[128 + j * 32 + lane];
        float4 xv = x4[j * 32 + lane];
        float4 vv;
        vv.x = a.x / (1.0f + expf(-g.x)) + xv.x;
        vv.y = a.y / (1.0f + expf(-g.y)) + xv.y;
        vv.z = a.z / (1.0f + expf(-g.z)) + xv.z;
        vv.w = a.w / (1.0f + expf(-g.w)) + xv.w;
        v[j] = vv;
        s += vv.x + vv.y + vv.z + vv.w;
        s2 = fmaf(vv.x, vv.x, s2); s2 = fmaf(vv.y, vv.y, s2);
        s2 = fmaf(vv.z, vv.z, s2); s2 = fmaf(vv.w, vv.w, s2);
    }
#pragma unroll
    for (int o = 16; o; o >>= 1) {
        s  += __shfl_xor_sync(0xffffffffu, s, o);
        s2 += __shfl_xor_sync(0xffffffffu, s2, o);
    }
    float mu = s * (1.0f / H);
    float rs = rsqrtf(s2 * (1.0f / H) - mu * mu + LN_EPS);
#pragma unroll
    for (int j = 0; j < 4; j++) {
        float4 ga = g4[j * 32 + lane];
        float4 be = e4[j * 32 + lane];
        float4 vv = v[j], o;
        o.x = (vv.x - mu) * rs * ga.x + be.x;
        o.y = (vv.y - mu) * rs * ga.y + be.y;
        o.z = (vv.z - mu) * rs * ga.z + be.z;
        o.w = (vv.w - mu) * rs * ga.w + be.w;
        o4[j * 32 + lane] = o;
    }
}

// ================= launcher =================
extern "C" void kernel_launch(void* const* d_in, const int* in_sizes, int n_in,
                              void* d_out, int out_size)
{
    const float* x          = (const float*)d_in[0];
    const float* log_dt     = (const float*)d_in[1];
    const float* A_imag     = (const float*)d_in[2];
    const float* log_A_real = (const float*)d_in[3];
    const float* C          = (const float*)d_in[4];
    const float* D          = (const float*)d_in[5];
    const float* W          = (const float*)d_in[6];
    const float* bconv      = (const float*)d_in[7];
    const float* gamma      = (const float*)d_in[8];
    const float* beta       = (const float*)d_in[9];
    float* out = (float*)d_out;

    float* pA; cudaGetSymbolAddress((void**)&pA, g_xA);
    float* pB; cudaGetSymbolAddress((void**)&pB, g_xB);

    const float* xin[NLAY]  = {x,  pA, pB, pA};
    float*       xout[NLAY] = {pA, pB, pA, out};

    for (int i = 0; i < NLAY; i++) {
        ssm_scan<<<BSZ * (H / 32), 256>>>(xin[i], log_dt, A_imag, log_A_real, C, D, i);
        conv_gemm<<<dim3(2 * H / GBN, MROWS / GBM), 256>>>(W, bconv, i);
        glu_ln<<<MROWS / 4, 128>>>(xin[i], xout[i], gamma, beta, i);
    }
}

// round 6
// speedup vs baseline: 2.3551x; 1.4033x over previous
#include <cuda_runtime.h>
#include <cuda_bf16.h>
#include <cstdint>

#define H    512
#define NLAY 4
#define N2   32
#define BSZ  8
#define LSEQ 4096
#define MROWS (BSZ * LSEQ)     /* 32768 */
#define NC   16                /* scan chunks */
#define CL   (LSEQ / NC)       /* 256 steps per chunk */
#define LN_EPS 1e-5f

typedef unsigned long long u64;

// ---- static scratch (allocation-free rule). layout (B,L,H) row-major ----
__device__ __align__(256) float g_xA[(size_t)MROWS * H];            // 64MB
__device__ __align__(256) float g_xB[(size_t)MROWS * H];            // 64MB
__device__ __align__(256) __nv_bfloat16 g_Yhi [(size_t)MROWS * H];  // 32MB
__device__ __align__(256) __nv_bfloat16 g_Ymid[(size_t)MROWS * H];  // 32MB
__device__ __align__(256) __nv_bfloat16 g_Whi [(size_t)NLAY * 2 * H * H]; // 4MB
__device__ __align__(256) __nv_bfloat16 g_Wmid[(size_t)NLAY * 2 * H * H]; // 4MB
__device__ __align__(256) float g_Z[(size_t)MROWS * 2 * H];         // 128MB
__device__ __align__(256) float g_E[(size_t)BSZ * NC * H * N2 * 2]; // 16MB end states
__device__ __align__(256) float g_S[(size_t)BSZ * NC * H * N2 * 2]; // 16MB init states

// ---------------- packed f32x2 helpers ----------------
__device__ __forceinline__ u64 pk(float lo, float hi) {
    u64 r; asm("mov.b64 %0, {%1,%2};" : "=l"(r) : "f"(lo), "f"(hi)); return r;
}
__device__ __forceinline__ void upk(u64 v, float& lo, float& hi) {
    asm("mov.b64 {%0,%1}, %2;" : "=f"(lo), "=f"(hi) : "l"(v));
}
__device__ __forceinline__ u64 fma2(u64 a, u64 b, u64 c) {
    u64 d; asm("fma.rn.f32x2 %0, %1, %2, %3;" : "=l"(d) : "l"(a), "l"(b), "l"(c)); return d;
}
__device__ __forceinline__ u64 mul2(u64 a, u64 b) {
    u64 d; asm("mul.rn.f32x2 %0, %1, %2;" : "=l"(d) : "l"(a), "l"(b)); return d;
}
__device__ __forceinline__ void cpa16(void* dst, const void* src) {
    unsigned d = (unsigned)__cvta_generic_to_shared(dst);
    asm volatile("cp.async.cg.shared.global [%0], [%1], 16;" :: "r"(d), "l"(src));
}

// =====================================================================
// Shared coefficient computation for the scan kernels
// =====================================================================
__device__ __forceinline__ void scan_coeffs(
    const float* log_dt, const float* A_imag, const float* log_A_real,
    int layer, int h, int li, float* w_re, float* w_im, float* Are_o, float* Aim_o,
    float* dt_o)
{
    float dt = expf(log_dt[layer * H + h]);
    int pbase = (layer * H + h) * N2 + li * 4;
    float4 aim = *(const float4*)(A_imag + pbase);
    float4 lar = *(const float4*)(log_A_real + pbase);
    float aimv[4] = {aim.x, aim.y, aim.z, aim.w};
    float larv[4] = {lar.x, lar.y, lar.z, lar.w};
#pragma unroll
    for (int j = 0; j < 4; j++) {
        float Are = -expf(larv[j]);
        float e = expf(Are * dt);
        w_re[j] = e * cosf(aimv[j] * dt);
        w_im[j] = e * sinf(aimv[j] * dt);
        Are_o[j] = Are; Aim_o[j] = aimv[j];
    }
    *dt_o = dt;
}

// =====================================================================
// Pass 1: chunk-local end states (zero init). grid (128, NC) x 256 thr.
// =====================================================================
__global__ __launch_bounds__(256) void ssm_pass1(
    const float* __restrict__ xin,
    const float* __restrict__ log_dt, const float* __restrict__ A_imag,
    const float* __restrict__ log_A_real, int layer)
{
    __shared__ float u_t[2][16][32];
    int tid = threadIdx.x;
    int b = blockIdx.x >> 4;
    int h0 = (blockIdx.x & 15) * 32;
    int c = blockIdx.y;
    int hloc = tid >> 3, li = tid & 7;
    int h = h0 + hloc;
    int lrow = tid >> 5, lcol = tid & 31;

    float w_re[4], w_im[4], Are[4], Aim[4], dt;
    scan_coeffs(log_dt, A_imag, log_A_real, layer, h, li, w_re, w_im, Are, Aim, &dt);
    u64 w2re[2]  = {pk(w_re[0], w_re[1]),  pk(w_re[2], w_re[3])};
    u64 w2im[2]  = {pk(w_im[0], w_im[1]),  pk(w_im[2], w_im[3])};
    u64 nw2im[2] = {pk(-w_im[0], -w_im[1]), pk(-w_im[2], -w_im[3])};

    const float* xr = xin + ((size_t)b * LSEQ + (size_t)c * CL) * H + h0;
    u_t[0][lrow][lcol]     = xr[(size_t)lrow * H + lcol];
    u_t[0][lrow + 8][lcol] = xr[(size_t)(lrow + 8) * H + lcol];
    __syncthreads();

    u64 s2re[2] = {0ull, 0ull}, s2im[2] = {0ull, 0ull};
    for (int it = 0; it < CL / 16; it++) {
        int buf = it & 1, l0 = it * 16;
        float p0 = 0.f, p1 = 0.f;
        if (it + 1 < CL / 16) {
            p0 = xr[(size_t)(l0 + 16 + lrow) * H + lcol];
            p1 = xr[(size_t)(l0 + 24 + lrow) * H + lcol];
        }
#pragma unroll
        for (int k = 0; k < 16; k++) {
            float u = u_t[buf][k][hloc];
            u64 u2 = pk(u, u);
            u64 nre0 = fma2(w2re[0], s2re[0], fma2(nw2im[0], s2im[0], u2));
            u64 nim0 = fma2(w2im[0], s2re[0], mul2(w2re[0], s2im[0]));
            s2re[0] = nre0; s2im[0] = nim0;
            u64 nre1 = fma2(w2re[1], s2re[1], fma2(nw2im[1], s2im[1], u2));
            u64 nim1 = fma2(w2im[1], s2re[1], mul2(w2re[1], s2im[1]));
            s2re[1] = nre1; s2im[1] = nim1;
        }
        if (it + 1 < CL / 16) {
            u_t[buf ^ 1][lrow][lcol] = p0;
            u_t[buf ^ 1][lrow + 8][lcol] = p1;
        }
        __syncthreads();
    }
    float r0, r1, r2, r3, i0, i1, i2, i3;
    upk(s2re[0], r0, r1); upk(s2re[1], r2, r3);
    upk(s2im[0], i0, i1); upk(s2im[1], i2, i3);
    float* Ep = g_E + ((((size_t)b * NC + c) * H + h) * 8 + li) * 8;
    ((float4*)Ep)[0] = make_float4(r0, i0, r1, i1);
    ((float4*)Ep)[1] = make_float4(r2, i2, r3, i3);
}

// =====================================================================
// Pass 2: prefix over chunks. (b,h,li) threads.
// =====================================================================
__global__ __launch_bounds__(256) void ssm_prefix(
    const float* __restrict__ log_dt, const float* __restrict__ A_imag,
    const float* __restrict__ log_A_real, int layer)
{
    int idx = blockIdx.x * 256 + threadIdx.x;
    int b = idx >> 12, rem = idx & 4095;
    int h = rem >> 3, li = rem & 7;

    float w_re[4], w_im[4], Are[4], Aim[4], dt;
    scan_coeffs(log_dt, A_imag, log_A_real, layer, h, li, w_re, w_im, Are, Aim, &dt);
    float Wr[4], Wi[4];
#pragma unroll
    for (int j = 0; j < 4; j++) {                  // w^CL = exp(dA*CL)
        float e = expf(Are[j] * dt * (float)CL);
        Wr[j] = e * cosf(Aim[j] * dt * (float)CL);
        Wi[j] = e * sinf(Aim[j] * dt * (float)CL);
    }
    float Ire[4] = {0,0,0,0}, Iim[4] = {0,0,0,0};
    for (int c = 0; c < NC; c++) {
        size_t off = ((((size_t)b * NC + c) * H + h) * 8 + li) * 8;
        float* Sp = g_S + off;
        ((float4*)Sp)[0] = make_float4(Ire[0], Iim[0], Ire[1], Iim[1]);
        ((float4*)Sp)[1] = make_float4(Ire[2], Iim[2], Ire[3], Iim[3]);
        const float* Ep = g_E + off;
        float4 e0 = ((const float4*)Ep)[0], e1 = ((const float4*)Ep)[1];
        float er[4] = {e0.x, e0.z, e1.x, e1.z};
        float ei[4] = {e0.y, e0.w, e1.y, e1.w};
#pragma unroll
        for (int j = 0; j < 4; j++) {
            float nr = fmaf(Wr[j], Ire[j], fmaf(-Wi[j], Iim[j], er[j]));
            float ni = fmaf(Wi[j], Ire[j], fmaf( Wr[j], Iim[j], ei[j]));
            Ire[j] = nr; Iim[j] = ni;
        }
    }
}

// =====================================================================
// Pass 3: full scan with init state, GELU, emit bf16 hi/mid planes.
// =====================================================================
__global__ __launch_bounds__(256) void ssm_pass3(
    const float* __restrict__ xin,
    const float* __restrict__ log_dt, const float* __restrict__ A_imag,
    const float* __restrict__ log_A_real, const float* __restrict__ Cp,
    const float* __restrict__ Dp, int layer)
{
    __shared__ float u_t[2][16][32];
    __shared__ float y_t[2][16][32];
    int tid = threadIdx.x;
    int b = blockIdx.x >> 4;
    int h0 = (blockIdx.x & 15) * 32;
    int c = blockIdx.y;
    int hloc = tid >> 3, li = tid & 7;
    int h = h0 + hloc;
    int lrow = tid >> 5, lcol = tid & 31;

    float w_re[4], w_im[4], Are[4], Aim[4], dt;
    scan_coeffs(log_dt, A_imag, log_A_real, layer, h, li, w_re, w_im, Are, Aim, &dt);
    int pbase = (layer * H + h) * N2 + li * 4;
    float4 c01 = *(const float4*)(Cp + 2 * pbase);
    float4 c23 = *(const float4*)(Cp + 2 * pbase + 4);
    float ccr[4] = {c01.x, c01.z, c23.x, c23.z};
    float cci[4] = {c01.y, c01.w, c23.y, c23.w};
    float cf_re[4], cf_im[4];
#pragma unroll
    for (int j = 0; j < 4; j++) {
        float nr = w_re[j] - 1.0f, ni = w_im[j];
        float tr = ccr[j] * nr - cci[j] * ni;
        float ti = ccr[j] * ni + cci[j] * nr;
        float inv = 2.0f / (Are[j] * Are[j] + Aim[j] * Aim[j]);
        cf_re[j] = (tr * Are[j] + ti * Aim[j]) * inv;
        cf_im[j] = (ti * Are[j] - tr * Aim[j]) * inv;
    }
    u64 w2re[2]  = {pk(w_re[0], w_re[1]),  pk(w_re[2], w_re[3])};
    u64 w2im[2]  = {pk(w_im[0], w_im[1]),  pk(w_im[2], w_im[3])};
    u64 nw2im[2] = {pk(-w_im[0], -w_im[1]), pk(-w_im[2], -w_im[3])};
    u64 cf2re[2] = {pk(cf_re[0], cf_re[1]), pk(cf_re[2], cf_re[3])};
    u64 ncf2im[2]= {pk(-cf_im[0], -cf_im[1]), pk(-cf_im[2], -cf_im[3])};
    float Dh = Dp[layer * H + h];

    const float* Sp = g_S + ((((size_t)b * NC + c) * H + h) * 8 + li) * 8;
    float4 sa = ((const float4*)Sp)[0], sb = ((const float4*)Sp)[1];
    u64 s2re[2] = {pk(sa.x, sa.z), pk(sb.x, sb.z)};
    u64 s2im[2] = {pk(sa.y, sa.w), pk(sb.y, sb.w)};

    const float* xr = xin + ((size_t)b * LSEQ + (size_t)c * CL) * H + h0;
    size_t yb = ((size_t)b * LSEQ + (size_t)c * CL) * H + h0;

    u_t[0][lrow][lcol]     = xr[(size_t)lrow * H + lcol];
    u_t[0][lrow + 8][lcol] = xr[(size_t)(lrow + 8) * H + lcol];
    __syncthreads();

    for (int it = 0; it < CL / 16; it++) {
        int buf = it & 1, l0 = it * 16;
        float p0 = 0.f, p1 = 0.f;
        if (it + 1 < CL / 16) {
            p0 = xr[(size_t)(l0 + 16 + lrow) * H + lcol];
            p1 = xr[(size_t)(l0 + 24 + lrow) * H + lcol];
        }
        float yl0 = 0.f, yl1 = 0.f;
#pragma unroll
        for (int k = 0; k < 16; k++) {
            float u = u_t[buf][k][hloc];
            u64 u2 = pk(u, u);
            u64 nre0 = fma2(w2re[0], s2re[0], fma2(nw2im[0], s2im[0], u2));
            u64 nim0 = fma2(w2im[0], s2re[0], mul2(w2re[0], s2im[0]));
            s2re[0] = nre0; s2im[0] = nim0;
            u64 c2 = mul2(cf2re[0], nre0);
            c2 = fma2(ncf2im[0], nim0, c2);
            u64 nre1 = fma2(w2re[1], s2re[1], fma2(nw2im[1], s2im[1], u2));
            u64 nim1 = fma2(w2im[1], s2re[1], mul2(w2re[1], s2im[1]));
            s2re[1] = nre1; s2im[1] = nim1;
            c2 = fma2(cf2re[1], nre1, c2);
            c2 = fma2(ncf2im[1], nim1, c2);
            float clo, chi; upk(c2, clo, chi);
            float cc = clo + chi;
            cc += __shfl_xor_sync(0xffffffffu, cc, 1);
            cc += __shfl_xor_sync(0xffffffffu, cc, 2);
            cc += __shfl_xor_sync(0xffffffffu, cc, 4);
            cc = fmaf(Dh, u, cc);
            if ((k & 7) == li) { if (k < 8) yl0 = cc; else yl1 = cc; }
        }
        yl0 = 0.5f * yl0 * (1.0f + erff(yl0 * 0.70710678118654752f));
        yl1 = 0.5f * yl1 * (1.0f + erff(yl1 * 0.70710678118654752f));
        y_t[buf][li][hloc] = yl0;
        y_t[buf][li + 8][hloc] = yl1;
        if (it + 1 < CL / 16) {
            u_t[buf ^ 1][lrow][lcol] = p0;
            u_t[buf ^ 1][lrow + 8][lcol] = p1;
        }
        __syncthreads();
        float v0 = y_t[buf][lrow][lcol];
        float v1 = y_t[buf][lrow + 8][lcol];
        size_t r0i = yb + (size_t)(l0 + lrow) * H + lcol;
        size_t r1i = r0i + 8 * H;
        __nv_bfloat16 h0b = __float2bfloat16(v0);
        g_Yhi[r0i] = h0b;
        g_Ymid[r0i] = __float2bfloat16(v0 - __bfloat162float(h0b));
        __nv_bfloat16 h1b = __float2bfloat16(v1);
        g_Yhi[r1i] = h1b;
        g_Ymid[r1i] = __float2bfloat16(v1 - __bfloat162float(h1b));
    }
}

// =====================================================================
// W prep: split into bf16 hi/mid planes (all layers).
// =====================================================================
__global__ __launch_bounds__(256) void w_prep(const float* __restrict__ W) {
    size_t i = (size_t)blockIdx.x * 256 + threadIdx.x;
    float v = W[i];
    __nv_bfloat16 hi = __float2bfloat16(v);
    g_Whi[i] = hi;
    g_Wmid[i] = __float2bfloat16(v - __bfloat162float(hi));
}

// =====================================================================
// GEMM: Z[32768,1024] = Y @ W^T, bf16 3-term split on mma.sync m16n8k16.
// CTA tile 128x128, K-tile 16, 2-stage cp.async, 256 threads.
// STATIC smem: 2 stages x 24576B = 49152B (<= 48KB static limit).
// smem row stride 48B -> 16B-aligned cp.async + conflict-free LDS.
// =====================================================================
#define PLANE 6144u            /* 128 rows * 48B */
#define BOFF  12288u           /* B planes start */
#define STAGE 24576u

__device__ __forceinline__ void mma_bf16(float* d, const uint32_t* a,
                                         uint32_t b0, uint32_t b1) {
    asm volatile(
        "mma.sync.aligned.m16n8k16.row.col.f32.bf16.bf16.f32 "
        "{%0,%1,%2,%3}, {%4,%5,%6,%7}, {%8,%9}, {%0,%1,%2,%3};"
        : "+f"(d[0]), "+f"(d[1]), "+f"(d[2]), "+f"(d[3])
        : "r"(a[0]), "r"(a[1]), "r"(a[2]), "r"(a[3]), "r"(b0), "r"(b1));
}

__global__ __launch_bounds__(256, 2) void conv_gemm(
    const float* __restrict__ bp, int layer)
{
    __shared__ __align__(16) char smbuf[2][STAGE];

    int tid = threadIdx.x;
    int warp = tid >> 5, lane = tid & 31;
    int grp = lane >> 2, tq = lane & 3;
    int n0 = blockIdx.x * 128, m0 = blockIdx.y * 128;

    const __nv_bfloat16* Wh = g_Whi  + (size_t)layer * 2 * H * H;
    const __nv_bfloat16* Wm = g_Wmid + (size_t)layer * 2 * H * H;

    int wm = (warp >> 1) * 32, wn = (warp & 1) * 64;
    float acc[2][8][4];
#pragma unroll
    for (int mi = 0; mi < 2; mi++)
#pragma unroll
        for (int ni = 0; ni < 8; ni++)
#pragma unroll
            for (int r = 0; r < 4; r++) acc[mi][ni][r] = 0.0f;

    int fr = tid >> 1, fch = tid & 1;   // 256 threads = 128 rows x 2 chunks

#define LOAD_STAGE(KT, S)                                                        \
    do {                                                                         \
        char* sb = smbuf[S] + (unsigned)(fr * 48 + fch * 16);                    \
        size_t soA = (size_t)(m0 + fr) * H + (KT) * 16 + fch * 8;                \
        size_t soB = (size_t)(n0 + fr) * H + (KT) * 16 + fch * 8;                \
        cpa16(sb,                g_Yhi + soA);                                   \
        cpa16(sb + PLANE,        g_Ymid + soA);                                  \
        cpa16(sb + BOFF,         Wh + soB);                                      \
        cpa16(sb + BOFF + PLANE, Wm + soB);                                      \
        asm volatile("cp.async.commit_group;" ::: "memory");                     \
    } while (0)

    LOAD_STAGE(0, 0);

    const int NKT = H / 16;   // 32
    for (int kt = 0; kt < NKT; kt++) {
        int s = kt & 1;
        if (kt + 1 < NKT) {
            LOAD_STAGE(kt + 1, s ^ 1);
            asm volatile("cp.async.wait_group 1;" ::: "memory");
        } else {
            asm volatile("cp.async.wait_group 0;" ::: "memory");
        }
        __syncthreads();

        const char* sb = smbuf[s];
        uint32_t ah[2][4], am[2][4];
#pragma unroll
        for (int mi = 0; mi < 2; mi++) {
            const char* pa = sb + (unsigned)((wm + mi * 16 + grp) * 48);
            ah[mi][0] = *(const uint32_t*)(pa + tq * 4);
            ah[mi][1] = *(const uint32_t*)(pa + 8 * 48 + tq * 4);
            ah[mi][2] = *(const uint32_t*)(pa + (tq + 4) * 4);
            ah[mi][3] = *(const uint32_t*)(pa + 8 * 48 + (tq + 4) * 4);
            am[mi][0] = *(const uint32_t*)(pa + PLANE + tq * 4);
            am[mi][1] = *(const uint32_t*)(pa + PLANE + 8 * 48 + tq * 4);
            am[mi][2] = *(const uint32_t*)(pa + PLANE + (tq + 4) * 4);
            am[mi][3] = *(const uint32_t*)(pa + PLANE + 8 * 48 + (tq + 4) * 4);
        }
#pragma unroll
        for (int ni = 0; ni < 8; ni++) {
            const char* pb = sb + BOFF + (unsigned)((wn + ni * 8 + grp) * 48);
            uint32_t bh0 = *(const uint32_t*)(pb + tq * 4);
            uint32_t bh1 = *(const uint32_t*)(pb + (tq + 4) * 4);
            uint32_t bm0 = *(const uint32_t*)(pb + PLANE + tq * 4);
            uint32_t bm1 = *(const uint32_t*)(pb + PLANE + (tq + 4) * 4);
#pragma unroll
            for (int mi = 0; mi < 2; mi++) {
                mma_bf16(acc[mi][ni], ah[mi], bh0, bh1);
                mma_bf16(acc[mi][ni], am[mi], bh0, bh1);
                mma_bf16(acc[mi][ni], ah[mi], bm0, bm1);
            }
        }
        __syncthreads();
    }

    // epilogue: bias (from gmem, L2-resident) + store Z
#pragma unroll
    for (int mi = 0; mi < 2; mi++)
#pragma unroll
        for (int ni = 0; ni < 8; ni++) {
            int r  = m0 + wm + mi * 16 + grp;
            int cb = wn + ni * 8 + tq * 2;
            float b0 = __ldg(bp + layer * 2 * H + n0 + cb);
            float b1 = __ldg(bp + layer * 2 * H + n0 + cb + 1);
            float2 v0 = {acc[mi][ni][0] + b0, acc[mi][ni][1] + b1};
            float2 v1 = {acc[mi][ni][2] + b0, acc[mi][ni][3] + b1};
            *(float2*)&g_Z[(size_t)r * (2 * H) + n0 + cb] = v0;
            *(float2*)&g_Z[(size_t)(r + 8) * (2 * H) + n0 + cb] = v1;
        }
}

// =====================================================================
// GLU + residual + LayerNorm. warp per row (512 contiguous floats).
// =====================================================================
__global__ __launch_bounds__(128) void glu_ln(
    const float* __restrict__ xin, float* __restrict__ xout,
    const float* __restrict__ gamma, const float* __restrict__ beta, int layer)
{
    int row  = blockIdx.x * 4 + (threadIdx.x >> 5);
    int lane = threadIdx.x & 31;
    const float4* z4 = (const float4*)(g_Z + (size_t)row * (2 * H));
    const float4* x4 = (const float4*)(xin + (size_t)row * H);
    float4* o4       = (float4*)(xout + (size_t)row * H);
    const float4* g4 = (const float4*)(gamma + layer * H);
    const float4* e4 = (const float4*)(beta + layer * H);

    float4 v[4];
    float s = 0.0f, s2 = 0.0f;
#pragma unroll
    for (int j = 0; j < 4; j++) {
        float4 a  = z4[j * 32 + lane];
        float4 g  = z4[128 + j * 32 + lane];
        float4 xv = x4[j * 32 + lane];
        float4 vv;
        vv.x = a.x / (1.0f + expf(-g.x)) + xv.x;
        vv.y = a.y / (1.0f + expf(-g.y)) + xv.y;
        vv.z = a.z / (1.0f + expf(-g.z)) + xv.z;
        vv.w = a.w / (1.0f + expf(-g.w)) + xv.w;
        v[j] = vv;
        s += vv.x + vv.y + vv.z + vv.w;
        s2 = fmaf(vv.x, vv.x, s2); s2 = fmaf(vv.y, vv.y, s2);
        s2 = fmaf(vv.z, vv.z, s2); s2 = fmaf(vv.w, vv.w, s2);
    }
#pragma unroll
    for (int o = 16; o; o >>= 1) {
        s  += __shfl_xor_sync(0xffffffffu, s, o);
        s2 += __shfl_xor_sync(0xffffffffu, s2, o);
    }
    float mu = s * (1.0f / H);
    float rs = rsqrtf(s2 * (1.0f / H) - mu * mu + LN_EPS);
#pragma unroll
    for (int j = 0; j < 4; j++) {
        float4 ga = g4[j * 32 + lane];
        float4 be = e4[j * 32 + lane];
        float4 vv = v[j], o;
        o.x = (vv.x - mu) * rs * ga.x + be.x;
        o.y = (vv.y - mu) * rs * ga.y + be.y;
        o.z = (vv.z - mu) * rs * ga.z + be.z;
        o.w = (vv.w - mu) * rs * ga.w + be.w;
        o4[j * 32 + lane] = o;
    }
}

// ================= launcher =================
extern "C" void kernel_launch(void* const* d_in, const int* in_sizes, int n_in,
                              void* d_out, int out_size)
{
    const float* x          = (const float*)d_in[0];
    const float* log_dt     = (const float*)d_in[1];
    const float* A_imag     = (const float*)d_in[2];
    const float* log_A_real = (const float*)d_in[3];
    const float* C          = (const float*)d_in[4];
    const float* D          = (const float*)d_in[5];
    const float* W          = (const float*)d_in[6];
    const float* bconv      = (const float*)d_in[7];
    const float* gamma      = (const float*)d_in[8];
    const float* beta       = (const float*)d_in[9];
    float* out = (float*)d_out;

    float* pA; cudaGetSymbolAddress((void**)&pA, g_xA);
    float* pB; cudaGetSymbolAddress((void**)&pB, g_xB);
    const float* xin[NLAY]  = {x,  pA, pB, pA};
    float*       xout[NLAY] = {pA, pB, pA, out};

    w_prep<<<(NLAY * 2 * H * H) / 256, 256>>>(W);

    for (int i = 0; i < NLAY; i++) {
        ssm_pass1<<<dim3(BSZ * (H / 32), NC), 256>>>(xin[i], log_dt, A_imag, log_A_real, i);
        ssm_prefix<<<BSZ * H * 8 / 256, 256>>>(log_dt, A_imag, log_A_real, i);
        ssm_pass3<<<dim3(BSZ * (H / 32), NC), 256>>>(xin[i], log_dt, A_imag, log_A_real,
                                                     C, D, i);
        conv_gemm<<<dim3(2 * H / 128, MROWS / 128), 256>>>(bconv, i);
        glu_ln<<<MROWS / 4, 128>>>(xin[i], xout[i], gamma, beta, i);
    }
}

// round 7
// speedup vs baseline: 2.3991x; 1.0187x over previous
#include <cuda_runtime.h>
#include <cuda_bf16.h>
#include <cstdint>

#define H    512
#define NLAY 4
#define N2   32
#define BSZ  8
#define LSEQ 4096
#define MROWS (BSZ * LSEQ)     /* 32768 */
#define NC   32                /* scan chunks */
#define CL   (LSEQ / NC)       /* 128 steps per chunk */
#define LN_EPS 1e-5f

typedef unsigned long long u64;

// ---- static scratch (allocation-free rule). layout (B,L,H) row-major ----
__device__ __align__(256) float g_xA[(size_t)MROWS * H];            // 64MB
__device__ __align__(256) float g_xB[(size_t)MROWS * H];            // 64MB
__device__ __align__(256) __nv_bfloat16 g_Yhi [(size_t)MROWS * H];  // 32MB
__device__ __align__(256) __nv_bfloat16 g_Ymid[(size_t)MROWS * H];  // 32MB
__device__ __align__(256) __nv_bfloat16 g_Whi [(size_t)NLAY * 2 * H * H]; // 4MB (interleaved rows)
__device__ __align__(256) __nv_bfloat16 g_Wmid[(size_t)NLAY * 2 * H * H]; // 4MB
__device__ __align__(256) float g_bint[NLAY * 2 * H];               // interleaved bias
__device__ __align__(256) float g_Z[(size_t)MROWS * H];             // 64MB GLU output
__device__ __align__(256) float g_E[(size_t)BSZ * NC * H * N2 * 2]; // 33.5MB end states
__device__ __align__(256) float g_S[(size_t)BSZ * NC * H * N2 * 2]; // 33.5MB init states

// ---------------- packed f32x2 helpers ----------------
__device__ __forceinline__ u64 pk(float lo, float hi) {
    u64 r; asm("mov.b64 %0, {%1,%2};" : "=l"(r) : "f"(lo), "f"(hi)); return r;
}
__device__ __forceinline__ void upk(u64 v, float& lo, float& hi) {
    asm("mov.b64 {%0,%1}, %2;" : "=f"(lo), "=f"(hi) : "l"(v));
}
__device__ __forceinline__ u64 fma2(u64 a, u64 b, u64 c) {
    u64 d; asm("fma.rn.f32x2 %0, %1, %2, %3;" : "=l"(d) : "l"(a), "l"(b), "l"(c)); return d;
}
__device__ __forceinline__ u64 mul2(u64 a, u64 b) {
    u64 d; asm("mul.rn.f32x2 %0, %1, %2;" : "=l"(d) : "l"(a), "l"(b)); return d;
}
__device__ __forceinline__ void cpa16(void* dst, const void* src) {
    unsigned d = (unsigned)__cvta_generic_to_shared(dst);
    asm volatile("cp.async.cg.shared.global [%0], [%1], 16;" :: "r"(d), "l"(src));
}

// =====================================================================
// Shared coefficient computation for the scan kernels
// =====================================================================
__device__ __forceinline__ void scan_coeffs(
    const float* log_dt, const float* A_imag, const float* log_A_real,
    int layer, int h, int li, float* w_re, float* w_im, float* Are_o, float* Aim_o,
    float* dt_o)
{
    float dt = expf(log_dt[layer * H + h]);
    int pbase = (layer * H + h) * N2 + li * 4;
    float4 aim = *(const float4*)(A_imag + pbase);
    float4 lar = *(const float4*)(log_A_real + pbase);
    float aimv[4] = {aim.x, aim.y, aim.z, aim.w};
    float larv[4] = {lar.x, lar.y, lar.z, lar.w};
#pragma unroll
    for (int j = 0; j < 4; j++) {
        float Are = -expf(larv[j]);
        float e = expf(Are * dt);
        w_re[j] = e * cosf(aimv[j] * dt);
        w_im[j] = e * sinf(aimv[j] * dt);
        Are_o[j] = Are; Aim_o[j] = aimv[j];
    }
    *dt_o = dt;
}

// =====================================================================
// Pass 1: chunk-local end states (zero init). grid (128, NC) x 256 thr.
// =====================================================================
__global__ __launch_bounds__(256) void ssm_pass1(
    const float* __restrict__ xin,
    const float* __restrict__ log_dt, const float* __restrict__ A_imag,
    const float* __restrict__ log_A_real, int layer)
{
    __shared__ float u_t[2][16][32];
    int tid = threadIdx.x;
    int b = blockIdx.x >> 4;
    int h0 = (blockIdx.x & 15) * 32;
    int c = blockIdx.y;
    int hloc = tid >> 3, li = tid & 7;
    int h = h0 + hloc;
    int lrow = tid >> 5, lcol = tid & 31;

    float w_re[4], w_im[4], Are[4], Aim[4], dt;
    scan_coeffs(log_dt, A_imag, log_A_real, layer, h, li, w_re, w_im, Are, Aim, &dt);
    u64 w2re[2]  = {pk(w_re[0], w_re[1]),  pk(w_re[2], w_re[3])};
    u64 w2im[2]  = {pk(w_im[0], w_im[1]),  pk(w_im[2], w_im[3])};
    u64 nw2im[2] = {pk(-w_im[0], -w_im[1]), pk(-w_im[2], -w_im[3])};

    const float* xr = xin + ((size_t)b * LSEQ + (size_t)c * CL) * H + h0;
    u_t[0][lrow][lcol]     = xr[(size_t)lrow * H + lcol];
    u_t[0][lrow + 8][lcol] = xr[(size_t)(lrow + 8) * H + lcol];
    __syncthreads();

    u64 s2re[2] = {0ull, 0ull}, s2im[2] = {0ull, 0ull};
    for (int it = 0; it < CL / 16; it++) {
        int buf = it & 1, l0 = it * 16;
        float p0 = 0.f, p1 = 0.f;
        if (it + 1 < CL / 16) {
            p0 = xr[(size_t)(l0 + 16 + lrow) * H + lcol];
            p1 = xr[(size_t)(l0 + 24 + lrow) * H + lcol];
        }
#pragma unroll
        for (int k = 0; k < 16; k++) {
            float u = u_t[buf][k][hloc];
            u64 u2 = pk(u, u);
            u64 nre0 = fma2(w2re[0], s2re[0], fma2(nw2im[0], s2im[0], u2));
            u64 nim0 = fma2(w2im[0], s2re[0], mul2(w2re[0], s2im[0]));
            s2re[0] = nre0; s2im[0] = nim0;
            u64 nre1 = fma2(w2re[1], s2re[1], fma2(nw2im[1], s2im[1], u2));
            u64 nim1 = fma2(w2im[1], s2re[1], mul2(w2re[1], s2im[1]));
            s2re[1] = nre1; s2im[1] = nim1;
        }
        if (it + 1 < CL / 16) {
            u_t[buf ^ 1][lrow][lcol] = p0;
            u_t[buf ^ 1][lrow + 8][lcol] = p1;
        }
        __syncthreads();
    }
    float r0, r1, r2, r3, i0, i1, i2, i3;
    upk(s2re[0], r0, r1); upk(s2re[1], r2, r3);
    upk(s2im[0], i0, i1); upk(s2im[1], i2, i3);
    float* Ep = g_E + ((((size_t)b * NC + c) * H + h) * 8 + li) * 8;
    ((float4*)Ep)[0] = make_float4(r0, i0, r1, i1);
    ((float4*)Ep)[1] = make_float4(r2, i2, r3, i3);
}

// =====================================================================
// Pass 2: prefix over chunks. (b,h,li) threads.
// =====================================================================
__global__ __launch_bounds__(256) void ssm_prefix(
    const float* __restrict__ log_dt, const float* __restrict__ A_imag,
    const float* __restrict__ log_A_real, int layer)
{
    int idx = blockIdx.x * 256 + threadIdx.x;
    int b = idx >> 12, rem = idx & 4095;
    int h = rem >> 3, li = rem & 7;

    float w_re[4], w_im[4], Are[4], Aim[4], dt;
    scan_coeffs(log_dt, A_imag, log_A_real, layer, h, li, w_re, w_im, Are, Aim, &dt);
    float Wr[4], Wi[4];
#pragma unroll
    for (int j = 0; j < 4; j++) {                  // w^CL = exp(dA*CL)
        float e = expf(Are[j] * dt * (float)CL);
        Wr[j] = e * cosf(Aim[j] * dt * (float)CL);
        Wi[j] = e * sinf(Aim[j] * dt * (float)CL);
    }
    float Ire[4] = {0,0,0,0}, Iim[4] = {0,0,0,0};
    for (int c = 0; c < NC; c++) {
        size_t off = ((((size_t)b * NC + c) * H + h) * 8 + li) * 8;
        float* Sp = g_S + off;
        ((float4*)Sp)[0] = make_float4(Ire[0], Iim[0], Ire[1], Iim[1]);
        ((float4*)Sp)[1] = make_float4(Ire[2], Iim[2], Ire[3], Iim[3]);
        const float* Ep = g_E + off;
        float4 e0 = ((const float4*)Ep)[0], e1 = ((const float4*)Ep)[1];
        float er[4] = {e0.x, e0.z, e1.x, e1.z};
        float ei[4] = {e0.y, e0.w, e1.y, e1.w};
#pragma unroll
        for (int j = 0; j < 4; j++) {
            float nr = fmaf(Wr[j], Ire[j], fmaf(-Wi[j], Iim[j], er[j]));
            float ni = fmaf(Wi[j], Ire[j], fmaf( Wr[j], Iim[j], ei[j]));
            Ire[j] = nr; Iim[j] = ni;
        }
    }
}

// =====================================================================
// Pass 3: full scan with init state, GELU, emit bf16 hi/mid planes.
// =====================================================================
__global__ __launch_bounds__(256) void ssm_pass3(
    const float* __restrict__ xin,
    const float* __restrict__ log_dt, const float* __restrict__ A_imag,
    const float* __restrict__ log_A_real, const float* __restrict__ Cp,
    const float* __restrict__ Dp, int layer)
{
    __shared__ float u_t[2][16][32];
    __shared__ float y_t[2][16][32];
    int tid = threadIdx.x;
    int b = blockIdx.x >> 4;
    int h0 = (blockIdx.x & 15) * 32;
    int c = blockIdx.y;
    int hloc = tid >> 3, li = tid & 7;
    int h = h0 + hloc;
    int lrow = tid >> 5, lcol = tid & 31;

    float w_re[4], w_im[4], Are[4], Aim[4], dt;
    scan_coeffs(log_dt, A_imag, log_A_real, layer, h, li, w_re, w_im, Are, Aim, &dt);
    int pbase = (layer * H + h) * N2 + li * 4;
    float4 c01 = *(const float4*)(Cp + 2 * pbase);
    float4 c23 = *(const float4*)(Cp + 2 * pbase + 4);
    float ccr[4] = {c01.x, c01.z, c23.x, c23.z};
    float cci[4] = {c01.y, c01.w, c23.y, c23.w};
    float cf_re[4], cf_im[4];
#pragma unroll
    for (int j = 0; j < 4; j++) {
        float nr = w_re[j] - 1.0f, ni = w_im[j];
        float tr = ccr[j] * nr - cci[j] * ni;
        float ti = ccr[j] * ni + cci[j] * nr;
        float inv = 2.0f / (Are[j] * Are[j] + Aim[j] * Aim[j]);
        cf_re[j] = (tr * Are[j] + ti * Aim[j]) * inv;
        cf_im[j] = (ti * Are[j] - tr * Aim[j]) * inv;
    }
    u64 w2re[2]  = {pk(w_re[0], w_re[1]),  pk(w_re[2], w_re[3])};
    u64 w2im[2]  = {pk(w_im[0], w_im[1]),  pk(w_im[2], w_im[3])};
    u64 nw2im[2] = {pk(-w_im[0], -w_im[1]), pk(-w_im[2], -w_im[3])};
    u64 cf2re[2] = {pk(cf_re[0], cf_re[1]), pk(cf_re[2], cf_re[3])};
    u64 ncf2im[2]= {pk(-cf_im[0], -cf_im[1]), pk(-cf_im[2], -cf_im[3])};
    float Dh = Dp[layer * H + h];

    const float* Sp = g_S + ((((size_t)b * NC + c) * H + h) * 8 + li) * 8;
    float4 sa = ((const float4*)Sp)[0], sb = ((const float4*)Sp)[1];
    u64 s2re[2] = {pk(sa.x, sa.z), pk(sb.x, sb.z)};
    u64 s2im[2] = {pk(sa.y, sa.w), pk(sb.y, sb.w)};

    const float* xr = xin + ((size_t)b * LSEQ + (size_t)c * CL) * H + h0;
    size_t yb = ((size_t)b * LSEQ + (size_t)c * CL) * H + h0;

    u_t[0][lrow][lcol]     = xr[(size_t)lrow * H + lcol];
    u_t[0][lrow + 8][lcol] = xr[(size_t)(lrow + 8) * H + lcol];
    __syncthreads();

    for (int it = 0; it < CL / 16; it++) {
        int buf = it & 1, l0 = it * 16;
        float p0 = 0.f, p1 = 0.f;
        if (it + 1 < CL / 16) {
            p0 = xr[(size_t)(l0 + 16 + lrow) * H + lcol];
            p1 = xr[(size_t)(l0 + 24 + lrow) * H + lcol];
        }
        float yl0 = 0.f, yl1 = 0.f;
#pragma unroll
        for (int k = 0; k < 16; k++) {
            float u = u_t[buf][k][hloc];
            u64 u2 = pk(u, u);
            u64 nre0 = fma2(w2re[0], s2re[0], fma2(nw2im[0], s2im[0], u2));
            u64 nim0 = fma2(w2im[0], s2re[0], mul2(w2re[0], s2im[0]));
            s2re[0] = nre0; s2im[0] = nim0;
            u64 c2 = mul2(cf2re[0], nre0);
            c2 = fma2(ncf2im[0], nim0, c2);
            u64 nre1 = fma2(w2re[1], s2re[1], fma2(nw2im[1], s2im[1], u2));
            u64 nim1 = fma2(w2im[1], s2re[1], mul2(w2re[1], s2im[1]));
            s2re[1] = nre1; s2im[1] = nim1;
            c2 = fma2(cf2re[1], nre1, c2);
            c2 = fma2(ncf2im[1], nim1, c2);
            float clo, chi; upk(c2, clo, chi);
            float cc = clo + chi;
            cc += __shfl_xor_sync(0xffffffffu, cc, 1);
            cc += __shfl_xor_sync(0xffffffffu, cc, 2);
            cc += __shfl_xor_sync(0xffffffffu, cc, 4);
            cc = fmaf(Dh, u, cc);
            if ((k & 7) == li) { if (k < 8) yl0 = cc; else yl1 = cc; }
        }
        yl0 = 0.5f * yl0 * (1.0f + erff(yl0 * 0.70710678118654752f));
        yl1 = 0.5f * yl1 * (1.0f + erff(yl1 * 0.70710678118654752f));
        y_t[buf][li][hloc] = yl0;
        y_t[buf][li + 8][hloc] = yl1;
        if (it + 1 < CL / 16) {
            u_t[buf ^ 1][lrow][lcol] = p0;
            u_t[buf ^ 1][lrow + 8][lcol] = p1;
        }
        __syncthreads();
        float v0 = y_t[buf][lrow][lcol];
        float v1 = y_t[buf][lrow + 8][lcol];
        size_t r0i = yb + (size_t)(l0 + lrow) * H + lcol;
        size_t r1i = r0i + 8 * H;
        __nv_bfloat16 h0b = __float2bfloat16(v0);
        g_Yhi[r0i] = h0b;
        g_Ymid[r0i] = __float2bfloat16(v0 - __bfloat162float(h0b));
        __nv_bfloat16 h1b = __float2bfloat16(v1);
        g_Yhi[r1i] = h1b;
        g_Ymid[r1i] = __float2bfloat16(v1 - __bfloat162float(h1b));
    }
}

// =====================================================================
// W prep: interleave rows (2i <- a-row i, 2i+1 <- g-row i+H) and split
// into bf16 hi/mid planes. Also interleave bias.
// =====================================================================
__global__ __launch_bounds__(256) void w_prep(const float* __restrict__ W,
                                              const float* __restrict__ bp) {
    size_t i = (size_t)blockIdx.x * 256 + threadIdx.x;   // over NLAY*2H*H
    int col = (int)(i % H);
    int k   = (int)((i / H) % (2 * H));
    int l   = (int)(i / ((size_t)H * 2 * H));
    int orig = (k >> 1) + (k & 1) * H;
    float v = W[((size_t)l * 2 * H + orig) * H + col];
    __nv_bfloat16 hi = __float2bfloat16(v);
    g_Whi[i] = hi;
    g_Wmid[i] = __float2bfloat16(v - __bfloat162float(hi));
    if (i < NLAY * 2 * H) {
        int kk = (int)(i % (2 * H));
        int ll = (int)(i / (2 * H));
        int og = (kk >> 1) + (kk & 1) * H;
        g_bint[i] = bp[ll * 2 * H + og];
    }
}

// =====================================================================
// GEMM + fused GLU: bf16 3-term split on mma.sync m16n8k16.
// CTA tile 128x128, K-tile 16, 3-stage cp.async (72KB dynamic smem),
// ONE __syncthreads per ktile. Epilogue computes a*sigmoid(g) directly
// (W rows interleaved so cols 2i,2i+1 = (a,g) of output channel i).
// =====================================================================
#define PLANE 6144u            /* 128 rows * 48B */
#define BOFF  12288u           /* B planes start */
#define STAGE 24576u
#define GEMM_DSMEM (3 * STAGE)  /* 73728 */

__device__ __forceinline__ void mma_bf16(float* d, const uint32_t* a,
                                         uint32_t b0, uint32_t b1) {
    asm volatile(
        "mma.sync.aligned.m16n8k16.row.col.f32.bf16.bf16.f32 "
        "{%0,%1,%2,%3}, {%4,%5,%6,%7}, {%8,%9}, {%0,%1,%2,%3};"
        : "+f"(d[0]), "+f"(d[1]), "+f"(d[2]), "+f"(d[3])
        : "r"(a[0]), "r"(a[1]), "r"(a[2]), "r"(a[3]), "r"(b0), "r"(b1));
}

__global__ __launch_bounds__(256, 2) void conv_gemm(int layer)
{
    extern __shared__ __align__(16) char dsm[];

    int tid = threadIdx.x;
    int warp = tid >> 5, lane = tid & 31;
    int grp = lane >> 2, tq = lane & 3;
    int n0 = blockIdx.x * 128, m0 = blockIdx.y * 128;

    const __nv_bfloat16* Wh = g_Whi  + (size_t)layer * 2 * H * H;
    const __nv_bfloat16* Wm = g_Wmid + (size_t)layer * 2 * H * H;

    int wm = (warp >> 1) * 32, wn = (warp & 1) * 64;
    float acc[2][8][4];
#pragma unroll
    for (int mi = 0; mi < 2; mi++)
#pragma unroll
        for (int ni = 0; ni < 8; ni++)
#pragma unroll
            for (int r = 0; r < 4; r++) acc[mi][ni][r] = 0.0f;

    int fr = tid >> 1, fch = tid & 1;   // 256 threads = 128 rows x 2 chunks

#define LOAD_STAGE(KT, S)                                                        \
    do {                                                                         \
        char* sb = dsm + (unsigned)(S) * STAGE + (unsigned)(fr * 48 + fch * 16); \
        size_t soA = (size_t)(m0 + fr) * H + (KT) * 16 + fch * 8;                \
        size_t soB = (size_t)(n0 + fr) * H + (KT) * 16 + fch * 8;                \
        cpa16(sb,                g_Yhi + soA);                                   \
        cpa16(sb + PLANE,        g_Ymid + soA);                                  \
        cpa16(sb + BOFF,         Wh + soB);                                      \
        cpa16(sb + BOFF + PLANE, Wm + soB);                                      \
        asm volatile("cp.async.commit_group;" ::: "memory");                     \
    } while (0)

    LOAD_STAGE(0, 0);
    LOAD_STAGE(1, 1);

    const int NKT = H / 16;   // 32
    for (int kt = 0; kt < NKT; kt++) {
        int s = kt - (kt / 3) * 3;   // kt % 3
        if (kt + 2 < NKT) asm volatile("cp.async.wait_group 1;" ::: "memory");
        else              asm volatile("cp.async.wait_group 0;" ::: "memory");
        __syncthreads();
        if (kt + 2 < NKT) {
            int s2 = (kt + 2) - ((kt + 2) / 3) * 3;
            LOAD_STAGE(kt + 2, s2);
        }

        const char* sb = dsm + (unsigned)s * STAGE;
        uint32_t ah[2][4], am[2][4];
#pragma unroll
        for (int mi = 0; mi < 2; mi++) {
            const char* pa = sb + (unsigned)((wm + mi * 16 + grp) * 48);
            ah[mi][0] = *(const uint32_t*)(pa + tq * 4);
            ah[mi][1] = *(const uint32_t*)(pa + 8 * 48 + tq * 4);
            ah[mi][2] = *(const uint32_t*)(pa + (tq + 4) * 4);
            ah[mi][3] = *(const uint32_t*)(pa + 8 * 48 + (tq + 4) * 4);
            am[mi][0] = *(const uint32_t*)(pa + PLANE + tq * 4);
            am[mi][1] = *(const uint32_t*)(pa + PLANE + 8 * 48 + tq * 4);
            am[mi][2] = *(const uint32_t*)(pa + PLANE + (tq + 4) * 4);
            am[mi][3] = *(const uint32_t*)(pa + PLANE + 8 * 48 + (tq + 4) * 4);
        }
#pragma unroll
        for (int ni = 0; ni < 8; ni++) {
            const char* pb = sb + BOFF + (unsigned)((wn + ni * 8 + grp) * 48);
            uint32_t bh0 = *(const uint32_t*)(pb + tq * 4);
            uint32_t bh1 = *(const uint32_t*)(pb + (tq + 4) * 4);
            uint32_t bm0 = *(const uint32_t*)(pb + PLANE + tq * 4);
            uint32_t bm1 = *(const uint32_t*)(pb + PLANE + (tq + 4) * 4);
#pragma unroll
            for (int mi = 0; mi < 2; mi++) {
                mma_bf16(acc[mi][ni], ah[mi], bh0, bh1);
                mma_bf16(acc[mi][ni], am[mi], bh0, bh1);
                mma_bf16(acc[mi][ni], ah[mi], bm0, bm1);
            }
        }
    }

    // epilogue: bias + GLU, store a*sigmoid(g) to g_Z (h-index = col/2)
#pragma unroll
    for (int mi = 0; mi < 2; mi++)
#pragma unroll
        for (int ni = 0; ni < 8; ni++) {
            int r  = m0 + wm + mi * 16 + grp;
            int cb = wn + ni * 8 + tq * 2;
            float ba = g_bint[layer * 2 * H + n0 + cb];
            float bg = g_bint[layer * 2 * H + n0 + cb + 1];
            float a0 = acc[mi][ni][0] + ba, gg0 = acc[mi][ni][1] + bg;
            float a1 = acc[mi][ni][2] + ba, gg1 = acc[mi][ni][3] + bg;
            int hidx = (n0 + cb) >> 1;
            g_Z[(size_t)r * H + hidx]       = a0 / (1.0f + expf(-gg0));
            g_Z[(size_t)(r + 8) * H + hidx] = a1 / (1.0f + expf(-gg1));
        }
}

// =====================================================================
// Residual + LayerNorm. warp per row (512 contiguous floats).
// =====================================================================
__global__ __launch_bounds__(128) void res_ln(
    const float* __restrict__ xin, float* __restrict__ xout,
    const float* __restrict__ gamma, const float* __restrict__ beta, int layer)
{
    int row  = blockIdx.x * 4 + (threadIdx.x >> 5);
    int lane = threadIdx.x & 31;
    const float4* z4 = (const float4*)(g_Z + (size_t)row * H);
    const float4* x4 = (const float4*)(xin + (size_t)row * H);
    float4* o4       = (float4*)(xout + (size_t)row * H);
    const float4* g4 = (const float4*)(gamma + layer * H);
    const float4* e4 = (const float4*)(beta + layer * H);

    float4 v[4];
    float s = 0.0f, s2 = 0.0f;
#pragma unroll
    for (int j = 0; j < 4; j++) {
        float4 zz = z4[j * 32 + lane];
        float4 xv = x4[j * 32 + lane];
        float4 vv;
        vv.x = zz.x + xv.x; vv.y = zz.y + xv.y;
        vv.z = zz.z + xv.z; vv.w = zz.w + xv.w;
        v[j] = vv;
        s += vv.x + vv.y + vv.z + vv.w;
        s2 = fmaf(vv.x, vv.x, s2); s2 = fmaf(vv.y, vv.y, s2);
        s2 = fmaf(vv.z, vv.z, s2); s2 = fmaf(vv.w, vv.w, s2);
    }
#pragma unroll
    for (int o = 16; o; o >>= 1) {
        s  += __shfl_xor_sync(0xffffffffu, s, o);
        s2 += __shfl_xor_sync(0xffffffffu, s2, o);
    }
    float mu = s * (1.0f / H);
    float rs = rsqrtf(s2 * (1.0f / H) - mu * mu + LN_EPS);
#pragma unroll
    for (int j = 0; j < 4; j++) {
        float4 ga = g4[j * 32 + lane];
        float4 be = e4[j * 32 + lane];
        float4 vv = v[j], o;
        o.x = (vv.x - mu) * rs * ga.x + be.x;
        o.y = (vv.y - mu) * rs * ga.y + be.y;
        o.z = (vv.z - mu) * rs * ga.z + be.z;
        o.w = (vv.w - mu) * rs * ga.w + be.w;
        o4[j * 32 + lane] = o;
    }
}

// ================= launcher =================
extern "C" void kernel_launch(void* const* d_in, const int* in_sizes, int n_in,
                              void* d_out, int out_size)
{
    const float* x          = (const float*)d_in[0];
    const float* log_dt     = (const float*)d_in[1];
    const float* A_imag     = (const float*)d_in[2];
    const float* log_A_real = (const float*)d_in[3];
    const float* C          = (const float*)d_in[4];
    const float* D          = (const float*)d_in[5];
    const float* W          = (const float*)d_in[6];
    const float* bconv      = (const float*)d_in[7];
    const float* gamma      = (const float*)d_in[8];
    const float* beta       = (const float*)d_in[9];
    float* out = (float*)d_out;

    cudaFuncSetAttribute(conv_gemm, cudaFuncAttributeMaxDynamicSharedMemorySize,
                         GEMM_DSMEM);

    float* pA; cudaGetSymbolAddress((void**)&pA, g_xA);
    float* pB; cudaGetSymbolAddress((void**)&pB, g_xB);
    const float* xin[NLAY]  = {x,  pA, pB, pA};
    float*       xout[NLAY] = {pA, pB, pA, out};

    w_prep<<<(NLAY * 2 * H * H) / 256, 256>>>(W, bconv);

    for (int i = 0; i < NLAY; i++) {
        ssm_pass1<<<dim3(BSZ * (H / 32), NC), 256>>>(xin[i], log_dt, A_imag, log_A_real, i);
        ssm_prefix<<<BSZ * H * 8 / 256, 256>>>(log_dt, A_imag, log_A_real, i);
        ssm_pass3<<<dim3(BSZ * (H / 32), NC), 256>>>(xin[i], log_dt, A_imag, log_A_real,
                                                     C, D, i);
        conv_gemm<<<dim3(2 * H / 128, MROWS / 128), 256, GEMM_DSMEM>>>(i);
        res_ln<<<MROWS / 4, 128>>>(xin[i], xout[i], gamma, beta, i);
    }
}